// round 7
// baseline (speedup 1.0000x reference)
#include <cuda_runtime.h>
#include <math.h>

#define INC 128
#define HID 64
#define MAXN 100000
#define MAXE 1600000
#define SCAN_B 256

__device__ int   g_deg [MAXN];
__device__ int   g_incl[MAXN];
__device__ int   g_bsum[512];
__device__ int   g_rowptr[MAXN + 1];
__device__ int   g_cur [MAXN];
__device__ int   g_csrc[MAXE];
__device__ float g_dinv[MAXN];
__device__ float g_feat1[(size_t)MAXN * HID];
__device__ float g_feat2[(size_t)MAXN * HID];

__global__ void k_deg(const int* __restrict__ ei, int E) {
    int e = blockIdx.x * blockDim.x + threadIdx.x;
    if (e < E) atomicAdd(&g_deg[ei[(size_t)E + e]], 1);
}

// Pass 1: per-block inclusive scan of deg (+ dinv)
__global__ void k_scan1(int n) {
    __shared__ int s[SCAN_B];
    int i = blockIdx.x * SCAN_B + threadIdx.x;
    int v = (i < n) ? g_deg[i] : 0;
    if (i < n) g_dinv[i] = rsqrtf((float)(v + 1));   // +1 self-loop
    s[threadIdx.x] = v;
    __syncthreads();
#pragma unroll
    for (int o = 1; o < SCAN_B; o <<= 1) {
        int t = 0;
        if (threadIdx.x >= o) t = s[threadIdx.x - o];
        __syncthreads();
        s[threadIdx.x] += t;
        __syncthreads();
    }
    if (i < n) g_incl[i] = s[threadIdx.x];
    if (threadIdx.x == SCAN_B - 1) g_bsum[blockIdx.x] = s[SCAN_B - 1];
}

// Pass 2 (fused): each block reduces bsum[0..bid) itself, then rowptr + cursors.
__global__ void k_finalize(int n) {
    __shared__ int red[256];
    int bid = blockIdx.x;
    int t = threadIdx.x;
    int p = 0;
    if (t < bid) p = g_bsum[t];
    if (t + 256 < bid) p += g_bsum[t + 256];
    red[t] = p;
    __syncthreads();
#pragma unroll
    for (int o = 128; o > 0; o >>= 1) {
        if (t < o) red[t] += red[t + o];
        __syncthreads();
    }
    int boff = red[0];
    int i = bid * 256 + t;
    if (i < n) {
        int incl = g_incl[i] + boff;
        g_rowptr[i + 1] = incl;
        g_cur[i] = incl - g_deg[i];
        if (i == 0) g_rowptr[0] = 0;
    }
}

__global__ void k_fill(const int* __restrict__ ei, int E) {
    int e = blockIdx.x * blockDim.x + threadIdx.x;
    if (e >= E) return;
    int d = ei[(size_t)E + e];
    int pos = atomicAdd(&g_cur[d], 1);
    g_csrc[pos] = ei[e];
}

// GEMM1: g_feat1 = dinv ⊙ (x @ W1). Double-buffered smem pipeline.
__global__ __launch_bounds__(256) void k_gemm1(const float* __restrict__ x,
                                               const float* __restrict__ W,
                                               int N) {
    __shared__ float As[2][128][33];
    __shared__ float Bs[2][32][64];
    int t = threadIdx.x;
    int row0 = blockIdx.x * 128;
    int rr = (t >> 4) * 8;
    int cc = (t & 15) * 4;
    float acc[8][4];
#pragma unroll
    for (int i = 0; i < 8; i++)
#pragma unroll
        for (int j = 0; j < 4; j++) acc[i][j] = 0.f;

    float4 pa[4], pb[2];

#define LDG_CHUNK(kc)                                                          \
    {                                                                          \
        _Pragma("unroll")                                                      \
        for (int j = 0; j < 4; j++) {                                          \
            int id = t + 256 * j;                                              \
            int r = id >> 3, k4 = id & 7;                                      \
            int grow = row0 + r;                                               \
            pa[j] = make_float4(0.f, 0.f, 0.f, 0.f);                           \
            if (grow < N)                                                      \
                pa[j] = *(const float4*)(x + (size_t)grow * INC + (kc) + k4 * 4); \
        }                                                                      \
        _Pragma("unroll")                                                      \
        for (int j = 0; j < 2; j++) {                                          \
            int id = t + 256 * j;                                              \
            int k = id >> 4, c4 = id & 15;                                     \
            pb[j] = *(const float4*)(W + (size_t)((kc) + k) * HID + c4 * 4);   \
        }                                                                      \
    }

#define STS_CHUNK(buf)                                                         \
    {                                                                          \
        _Pragma("unroll")                                                      \
        for (int j = 0; j < 4; j++) {                                          \
            int id = t + 256 * j;                                              \
            int r = id >> 3, k4 = id & 7;                                      \
            As[buf][r][k4 * 4 + 0] = pa[j].x; As[buf][r][k4 * 4 + 1] = pa[j].y; \
            As[buf][r][k4 * 4 + 2] = pa[j].z; As[buf][r][k4 * 4 + 3] = pa[j].w; \
        }                                                                      \
        _Pragma("unroll")                                                      \
        for (int j = 0; j < 2; j++) {                                          \
            int id = t + 256 * j;                                              \
            int k = id >> 4, c4 = id & 15;                                     \
            *(float4*)(&Bs[buf][k][c4 * 4]) = pb[j];                           \
        }                                                                      \
    }

    LDG_CHUNK(0);
    STS_CHUNK(0);
    __syncthreads();

#pragma unroll
    for (int kc = 0; kc < 4; kc++) {
        int cur = kc & 1;
        if (kc < 3) LDG_CHUNK((kc + 1) * 32);
#pragma unroll
        for (int k = 0; k < 32; k++) {
            float4 bv = *(const float4*)(&Bs[cur][k][cc]);
            float a[8];
#pragma unroll
            for (int i = 0; i < 8; i++) a[i] = As[cur][rr + i][k];
#pragma unroll
            for (int i = 0; i < 8; i++) {
                acc[i][0] += a[i] * bv.x; acc[i][1] += a[i] * bv.y;
                acc[i][2] += a[i] * bv.z; acc[i][3] += a[i] * bv.w;
            }
        }
        if (kc < 3) STS_CHUNK(cur ^ 1);
        __syncthreads();
    }
#undef LDG_CHUNK
#undef STS_CHUNK

#pragma unroll
    for (int i = 0; i < 8; i++) {
        int grow = row0 + rr + i;
        if (grow < N) {
            float s = g_dinv[grow];
            float4 o = make_float4(acc[i][0] * s, acc[i][1] * s, acc[i][2] * s, acc[i][3] * s);
            *(float4*)(g_feat1 + (size_t)grow * HID + cc) = o;
        }
    }
}

// FUSED: agg1 gather + h1 = relu(dinv*acc + b1) + feat2 = dinv*(h1 @ W2)
// Warp per node; W2 staged in smem; h broadcast via shfl.
__global__ __launch_bounds__(256) void k_agg1_gemm2(const float* __restrict__ b1,
                                                    const float* __restrict__ W2,
                                                    int N) {
    __shared__ float Ws[64][64];     // 16KB
    __shared__ float b1s[64];
    int tid = threadIdx.x;
#pragma unroll
    for (int j = 0; j < 4; j++) {
        int id = tid + 256 * j;       // 1024 float4 = 4096 floats
        ((float4*)Ws)[id] = ((const float4*)W2)[id];
    }
    if (tid < 64) b1s[tid] = b1[tid];
    __syncthreads();

    int v = (blockIdx.x * 256 + tid) >> 5;
    if (v >= N) return;
    int lane = tid & 31;
    int beg = g_rowptr[v];
    int end = g_rowptr[v + 1];

    float2 acc = *(const float2*)(g_feat1 + (size_t)v * HID + lane * 2);  // self-loop

    for (int b = beg; b < end; b += 32) {
        int n = end - b;
        if (n > 32) n = 32;
        int s = (lane < n) ? g_csrc[b + lane] : 0;
#pragma unroll 4
        for (int j = 0; j < n; j++) {
            int sj = __shfl_sync(0xffffffffu, s, j);
            float2 w = *(const float2*)(g_feat1 + (size_t)sj * HID + lane * 2);
            acc.x += w.x;
            acc.y += w.y;
        }
    }

    float dv = g_dinv[v];
    float h0 = fmaxf(fmaf(acc.x, dv, b1s[lane * 2 + 0]), 0.f);
    float h1 = fmaxf(fmaf(acc.y, dv, b1s[lane * 2 + 1]), 0.f);

    float o0 = 0.f, o1 = 0.f;
#pragma unroll
    for (int k2 = 0; k2 < 32; k2++) {
        float hh0 = __shfl_sync(0xffffffffu, h0, k2);
        float hh1 = __shfl_sync(0xffffffffu, h1, k2);
        float2 wa = *(const float2*)&Ws[2 * k2 + 0][lane * 2];
        float2 wb = *(const float2*)&Ws[2 * k2 + 1][lane * 2];
        o0 = fmaf(hh0, wa.x, fmaf(hh1, wb.x, o0));
        o1 = fmaf(hh0, wa.y, fmaf(hh1, wb.y, o1));
    }
    *(float2*)(g_feat2 + (size_t)v * HID + lane * 2) = make_float2(o0 * dv, o1 * dv);
}

// Layer-2 aggregate FUSED with classifier.
__global__ __launch_bounds__(256) void k_agg_out(const float* __restrict__ b2,
                                                 const float* __restrict__ Wc,
                                                 const float* __restrict__ bc,
                                                 float* __restrict__ out, int N) {
    int gtid = blockIdx.x * blockDim.x + threadIdx.x;
    int v = gtid >> 5;
    if (v >= N) return;
    int lane = threadIdx.x & 31;
    int beg = g_rowptr[v];
    int end = g_rowptr[v + 1];

    float2 acc = *(const float2*)(g_feat2 + (size_t)v * HID + lane * 2);

    for (int b = beg; b < end; b += 32) {
        int n = end - b;
        if (n > 32) n = 32;
        int s = (lane < n) ? g_csrc[b + lane] : 0;
#pragma unroll 4
        for (int j = 0; j < n; j++) {
            int sj = __shfl_sync(0xffffffffu, s, j);
            float2 w = *(const float2*)(g_feat2 + (size_t)sj * HID + lane * 2);
            acc.x += w.x;
            acc.y += w.y;
        }
    }
    float dv = g_dinv[v];
    float h0 = fmaxf(fmaf(acc.x, dv, __ldg(b2 + lane * 2 + 0)), 0.f);
    float h1 = fmaxf(fmaf(acc.y, dv, __ldg(b2 + lane * 2 + 1)), 0.f);
    float p = h0 * __ldg(Wc + lane * 2) + h1 * __ldg(Wc + lane * 2 + 1);
#pragma unroll
    for (int o = 16; o > 0; o >>= 1) p += __shfl_down_sync(0xffffffffu, p, o);
    if (lane == 0) out[v] = p + __ldg(bc);
}

extern "C" void kernel_launch(void* const* d_in, const int* in_sizes, int n_in,
                              void* d_out, int out_size) {
    const float* x  = (const float*)d_in[0];
    const int*   ei = (const int*)d_in[1];
    const float* W1 = (const float*)d_in[2];
    const float* b1 = (const float*)d_in[3];
    const float* W2 = (const float*)d_in[4];
    const float* b2 = (const float*)d_in[5];
    const float* Wc = (const float*)d_in[6];
    const float* bc = (const float*)d_in[7];
    float* out = (float*)d_out;

    int N = in_sizes[0] / INC;
    int E = in_sizes[1] / 2;
    int nb = (N + SCAN_B - 1) / SCAN_B;

    // CSR build + dinv
    void* degp = 0;
    cudaGetSymbolAddress(&degp, g_deg);
    cudaMemsetAsync(degp, 0, (size_t)N * sizeof(int));
    k_deg<<<(E + 255) / 256, 256>>>(ei, E);
    k_scan1<<<nb, SCAN_B>>>(N);
    k_finalize<<<nb, 256>>>(N);
    k_fill<<<(E + 255) / 256, 256>>>(ei, E);

    // Layer 1 GEMM
    k_gemm1<<<(N + 127) / 128, 256>>>(x, W1, N);
    // Aggregate 1 + layer-2 GEMM (fused)
    k_agg1_gemm2<<<(N * 32 + 255) / 256, 256>>>(b1, W2, N);
    // Aggregate 2 + classifier (fused)
    k_agg_out<<<(N * 32 + 255) / 256, 256>>>(b2, Wc, bc, out, N);
}

// round 8
// speedup vs baseline: 1.1925x; 1.1925x over previous
#include <cuda_runtime.h>
#include <math.h>

#define INC 128
#define HID 64
#define MAXN 100000
#define MAXE 1600000
#define SCAN_B 256

__device__ int   g_deg [MAXN];
__device__ int   g_incl[MAXN];
__device__ int   g_bsum[512];
__device__ int   g_rowptr[MAXN + 1];
__device__ int   g_rank[MAXE];
__device__ int   g_csrc[MAXE];
__device__ float g_dinv[MAXN];
__device__ float g_feat1[(size_t)MAXN * HID];
__device__ float g_agg1 [(size_t)MAXN * HID];
__device__ float g_feat2[(size_t)MAXN * HID];

// Degree count; atomic return value = edge's rank within its dst bucket.
__global__ void k_deg(const int* __restrict__ ei, int E) {
    int e = blockIdx.x * blockDim.x + threadIdx.x;
    if (e < E) g_rank[e] = atomicAdd(&g_deg[ei[(size_t)E + e]], 1);
}

// Pass 1: per-block inclusive scan of deg (+ dinv)
__global__ void k_scan1(int n) {
    __shared__ int s[SCAN_B];
    int i = blockIdx.x * SCAN_B + threadIdx.x;
    int v = (i < n) ? g_deg[i] : 0;
    if (i < n) g_dinv[i] = rsqrtf((float)(v + 1));   // +1 self-loop
    s[threadIdx.x] = v;
    __syncthreads();
#pragma unroll
    for (int o = 1; o < SCAN_B; o <<= 1) {
        int t = 0;
        if (threadIdx.x >= o) t = s[threadIdx.x - o];
        __syncthreads();
        s[threadIdx.x] += t;
        __syncthreads();
    }
    if (i < n) g_incl[i] = s[threadIdx.x];
    if (threadIdx.x == SCAN_B - 1) g_bsum[blockIdx.x] = s[SCAN_B - 1];
}

// Pass 2 (fused): each block reduces bsum[0..bid) itself, then writes rowptr.
__global__ void k_finalize(int n) {
    __shared__ int red[256];
    int bid = blockIdx.x;
    int t = threadIdx.x;
    int p = 0;
    if (t < bid) p = g_bsum[t];
    if (t + 256 < bid) p += g_bsum[t + 256];
    red[t] = p;
    __syncthreads();
#pragma unroll
    for (int o = 128; o > 0; o >>= 1) {
        if (t < o) red[t] += red[t + o];
        __syncthreads();
    }
    int boff = red[0];
    int i = bid * 256 + t;
    if (i < n) {
        g_rowptr[i + 1] = g_incl[i] + boff;
        if (i == 0) g_rowptr[0] = 0;
    }
}

// Atomic-free fill: pos = rowptr[dst] + rank (exclusive prefix = incl - deg ... rowptr[d] is
// exclusive start since rowptr[d+1] is inclusive end; rank in [0, deg).
__global__ void k_fill(const int* __restrict__ ei, int E) {
    int e = blockIdx.x * blockDim.x + threadIdx.x;
    if (e >= E) return;
    int d = ei[(size_t)E + e];
    g_csrc[g_rowptr[d] + g_rank[e]] = ei[e];
}

// GEMM1: g_feat1 = dinv ⊙ (x @ W1). Double-buffered smem pipeline.
__global__ __launch_bounds__(256) void k_gemm1(const float* __restrict__ x,
                                               const float* __restrict__ W,
                                               int N) {
    __shared__ float As[2][128][33];
    __shared__ float Bs[2][32][64];
    int t = threadIdx.x;
    int row0 = blockIdx.x * 128;
    int rr = (t >> 4) * 8;
    int cc = (t & 15) * 4;
    float acc[8][4];
#pragma unroll
    for (int i = 0; i < 8; i++)
#pragma unroll
        for (int j = 0; j < 4; j++) acc[i][j] = 0.f;

    float4 pa[4], pb[2];

#define LDG_CHUNK(kc)                                                          \
    {                                                                          \
        _Pragma("unroll")                                                      \
        for (int j = 0; j < 4; j++) {                                          \
            int id = t + 256 * j;                                              \
            int r = id >> 3, k4 = id & 7;                                      \
            int grow = row0 + r;                                               \
            pa[j] = make_float4(0.f, 0.f, 0.f, 0.f);                           \
            if (grow < N)                                                      \
                pa[j] = *(const float4*)(x + (size_t)grow * INC + (kc) + k4 * 4); \
        }                                                                      \
        _Pragma("unroll")                                                      \
        for (int j = 0; j < 2; j++) {                                          \
            int id = t + 256 * j;                                              \
            int k = id >> 4, c4 = id & 15;                                     \
            pb[j] = *(const float4*)(W + (size_t)((kc) + k) * HID + c4 * 4);   \
        }                                                                      \
    }

#define STS_CHUNK(buf)                                                         \
    {                                                                          \
        _Pragma("unroll")                                                      \
        for (int j = 0; j < 4; j++) {                                          \
            int id = t + 256 * j;                                              \
            int r = id >> 3, k4 = id & 7;                                      \
            As[buf][r][k4 * 4 + 0] = pa[j].x; As[buf][r][k4 * 4 + 1] = pa[j].y; \
            As[buf][r][k4 * 4 + 2] = pa[j].z; As[buf][r][k4 * 4 + 3] = pa[j].w; \
        }                                                                      \
        _Pragma("unroll")                                                      \
        for (int j = 0; j < 2; j++) {                                          \
            int id = t + 256 * j;                                              \
            int k = id >> 4, c4 = id & 15;                                     \
            *(float4*)(&Bs[buf][k][c4 * 4]) = pb[j];                           \
        }                                                                      \
    }

    LDG_CHUNK(0);
    STS_CHUNK(0);
    __syncthreads();

#pragma unroll
    for (int kc = 0; kc < 4; kc++) {
        int cur = kc & 1;
        if (kc < 3) LDG_CHUNK((kc + 1) * 32);
#pragma unroll
        for (int k = 0; k < 32; k++) {
            float4 bv = *(const float4*)(&Bs[cur][k][cc]);
            float a[8];
#pragma unroll
            for (int i = 0; i < 8; i++) a[i] = As[cur][rr + i][k];
#pragma unroll
            for (int i = 0; i < 8; i++) {
                acc[i][0] += a[i] * bv.x; acc[i][1] += a[i] * bv.y;
                acc[i][2] += a[i] * bv.z; acc[i][3] += a[i] * bv.w;
            }
        }
        if (kc < 3) STS_CHUNK(cur ^ 1);
        __syncthreads();
    }
#undef LDG_CHUNK
#undef STS_CHUNK

#pragma unroll
    for (int i = 0; i < 8; i++) {
        int grow = row0 + rr + i;
        if (grow < N) {
            float s = g_dinv[grow];
            float4 o = make_float4(acc[i][0] * s, acc[i][1] * s, acc[i][2] * s, acc[i][3] * s);
            *(float4*)(g_feat1 + (size_t)grow * HID + cc) = o;
        }
    }
}

// Layer-1 aggregate: g_agg1[v] = feat1[v] + sum_{src} feat1[src]
__global__ __launch_bounds__(256) void k_aggregate1(int N) {
    int gtid = blockIdx.x * blockDim.x + threadIdx.x;
    int v = gtid >> 5;
    if (v >= N) return;
    int lane = threadIdx.x & 31;
    int beg = g_rowptr[v];
    int end = g_rowptr[v + 1];

    float2 acc = *(const float2*)(g_feat1 + (size_t)v * HID + lane * 2);

    for (int b = beg; b < end; b += 32) {
        int n = end - b;
        if (n > 32) n = 32;
        int s = (lane < n) ? g_csrc[b + lane] : 0;
#pragma unroll 4
        for (int j = 0; j < n; j++) {
            int sj = __shfl_sync(0xffffffffu, s, j);
            float2 w = *(const float2*)(g_feat1 + (size_t)sj * HID + lane * 2);
            acc.x += w.x;
            acc.y += w.y;
        }
    }
    *(float2*)(g_agg1 + (size_t)v * HID + lane * 2) = acc;
}

// GEMM2: h1 = relu(dinv ⊙ agg1 + b1);  g_feat2 = dinv ⊙ (h1 @ W2). Double-buffered.
__global__ __launch_bounds__(256) void k_gemm2(const float* __restrict__ W,
                                               const float* __restrict__ b1,
                                               int N) {
    __shared__ float As[2][128][33];
    __shared__ float Bs[2][32][64];
    int t = threadIdx.x;
    int row0 = blockIdx.x * 128;
    int rr = (t >> 4) * 8;
    int cc = (t & 15) * 4;
    float acc[8][4];
#pragma unroll
    for (int i = 0; i < 8; i++)
#pragma unroll
        for (int j = 0; j < 4; j++) acc[i][j] = 0.f;

    float4 pa[4], pb[2];

#define LDG_CHUNK2(kc)                                                          \
    {                                                                           \
        _Pragma("unroll")                                                       \
        for (int j = 0; j < 4; j++) {                                           \
            int id = t + 256 * j;                                               \
            int r = id >> 3, k4 = id & 7;                                       \
            int grow = row0 + r;                                                \
            pa[j] = make_float4(0.f, 0.f, 0.f, 0.f);                            \
            if (grow < N) {                                                     \
                float4 v = *(const float4*)(g_agg1 + (size_t)grow * HID + (kc) + k4 * 4); \
                float dv = g_dinv[grow];                                        \
                pa[j].x = fmaxf(fmaf(v.x, dv, __ldg(b1 + (kc) + k4 * 4 + 0)), 0.f); \
                pa[j].y = fmaxf(fmaf(v.y, dv, __ldg(b1 + (kc) + k4 * 4 + 1)), 0.f); \
                pa[j].z = fmaxf(fmaf(v.z, dv, __ldg(b1 + (kc) + k4 * 4 + 2)), 0.f); \
                pa[j].w = fmaxf(fmaf(v.w, dv, __ldg(b1 + (kc) + k4 * 4 + 3)), 0.f); \
            }                                                                   \
        }                                                                       \
        _Pragma("unroll")                                                       \
        for (int j = 0; j < 2; j++) {                                           \
            int id = t + 256 * j;                                               \
            int k = id >> 4, c4 = id & 15;                                      \
            pb[j] = *(const float4*)(W + (size_t)((kc) + k) * HID + c4 * 4);    \
        }                                                                       \
    }

#define STS_CHUNK2(buf)                                                         \
    {                                                                           \
        _Pragma("unroll")                                                       \
        for (int j = 0; j < 4; j++) {                                           \
            int id = t + 256 * j;                                               \
            int r = id >> 3, k4 = id & 7;                                       \
            As[buf][r][k4 * 4 + 0] = pa[j].x; As[buf][r][k4 * 4 + 1] = pa[j].y; \
            As[buf][r][k4 * 4 + 2] = pa[j].z; As[buf][r][k4 * 4 + 3] = pa[j].w; \
        }                                                                       \
        _Pragma("unroll")                                                       \
        for (int j = 0; j < 2; j++) {                                           \
            int id = t + 256 * j;                                               \
            int k = id >> 4, c4 = id & 15;                                      \
            *(float4*)(&Bs[buf][k][c4 * 4]) = pb[j];                            \
        }                                                                       \
    }

    LDG_CHUNK2(0);
    STS_CHUNK2(0);
    __syncthreads();

#pragma unroll
    for (int kc = 0; kc < 2; kc++) {
        int cur = kc & 1;
        if (kc < 1) LDG_CHUNK2(32);
#pragma unroll
        for (int k = 0; k < 32; k++) {
            float4 bv = *(const float4*)(&Bs[cur][k][cc]);
            float a[8];
#pragma unroll
            for (int i = 0; i < 8; i++) a[i] = As[cur][rr + i][k];
#pragma unroll
            for (int i = 0; i < 8; i++) {
                acc[i][0] += a[i] * bv.x; acc[i][1] += a[i] * bv.y;
                acc[i][2] += a[i] * bv.z; acc[i][3] += a[i] * bv.w;
            }
        }
        if (kc < 1) STS_CHUNK2(cur ^ 1);
        __syncthreads();
    }
#undef LDG_CHUNK2
#undef STS_CHUNK2

#pragma unroll
    for (int i = 0; i < 8; i++) {
        int grow = row0 + rr + i;
        if (grow < N) {
            float s = g_dinv[grow];
            float4 o = make_float4(acc[i][0] * s, acc[i][1] * s, acc[i][2] * s, acc[i][3] * s);
            *(float4*)(g_feat2 + (size_t)grow * HID + cc) = o;
        }
    }
}

// Layer-2 aggregate FUSED with classifier.
__global__ __launch_bounds__(256) void k_agg_out(const float* __restrict__ b2,
                                                 const float* __restrict__ Wc,
                                                 const float* __restrict__ bc,
                                                 float* __restrict__ out, int N) {
    int gtid = blockIdx.x * blockDim.x + threadIdx.x;
    int v = gtid >> 5;
    if (v >= N) return;
    int lane = threadIdx.x & 31;
    int beg = g_rowptr[v];
    int end = g_rowptr[v + 1];

    float2 acc = *(const float2*)(g_feat2 + (size_t)v * HID + lane * 2);

    for (int b = beg; b < end; b += 32) {
        int n = end - b;
        if (n > 32) n = 32;
        int s = (lane < n) ? g_csrc[b + lane] : 0;
#pragma unroll 4
        for (int j = 0; j < n; j++) {
            int sj = __shfl_sync(0xffffffffu, s, j);
            float2 w = *(const float2*)(g_feat2 + (size_t)sj * HID + lane * 2);
            acc.x += w.x;
            acc.y += w.y;
        }
    }
    float dv = g_dinv[v];
    float h0 = fmaxf(fmaf(acc.x, dv, __ldg(b2 + lane * 2 + 0)), 0.f);
    float h1 = fmaxf(fmaf(acc.y, dv, __ldg(b2 + lane * 2 + 1)), 0.f);
    float p = h0 * __ldg(Wc + lane * 2) + h1 * __ldg(Wc + lane * 2 + 1);
#pragma unroll
    for (int o = 16; o > 0; o >>= 1) p += __shfl_down_sync(0xffffffffu, p, o);
    if (lane == 0) out[v] = p + __ldg(bc);
}

extern "C" void kernel_launch(void* const* d_in, const int* in_sizes, int n_in,
                              void* d_out, int out_size) {
    const float* x  = (const float*)d_in[0];
    const int*   ei = (const int*)d_in[1];
    const float* W1 = (const float*)d_in[2];
    const float* b1 = (const float*)d_in[3];
    const float* W2 = (const float*)d_in[4];
    const float* b2 = (const float*)d_in[5];
    const float* Wc = (const float*)d_in[6];
    const float* bc = (const float*)d_in[7];
    float* out = (float*)d_out;

    int N = in_sizes[0] / INC;
    int E = in_sizes[1] / 2;
    int nb = (N + SCAN_B - 1) / SCAN_B;

    // CSR build + dinv
    void* degp = 0;
    cudaGetSymbolAddress(&degp, g_deg);
    cudaMemsetAsync(degp, 0, (size_t)N * sizeof(int));
    k_deg<<<(E + 255) / 256, 256>>>(ei, E);
    k_scan1<<<nb, SCAN_B>>>(N);
    k_finalize<<<nb, 256>>>(N);
    k_fill<<<(E + 255) / 256, 256>>>(ei, E);

    // Layer 1
    k_gemm1<<<(N + 127) / 128, 256>>>(x, W1, N);
    k_aggregate1<<<(N * 32 + 255) / 256, 256>>>(N);

    // Layer 2 (+ fused classifier)
    k_gemm2<<<(N + 127) / 128, 256>>>(W2, b1, N);
    k_agg_out<<<(N * 32 + 255) / 256, 256>>>(b2, Wc, bc, out, N);
}

// round 9
// speedup vs baseline: 1.2128x; 1.0170x over previous
#include <cuda_runtime.h>
#include <math.h>

#define INC 128
#define HID 64
#define MAXN 100000
#define MAXE 1600000
#define SCAN_B 256

__device__ int   g_deg [MAXN];
__device__ int   g_incl[MAXN];
__device__ int   g_bsum[512];
__device__ int   g_rowptr[MAXN + 1];
__device__ int   g_rank[MAXE];
__device__ int   g_csrc[MAXE];
__device__ float g_dinv[MAXN];
__device__ float g_feat1[(size_t)MAXN * HID];
__device__ float g_agg1 [(size_t)MAXN * HID];
__device__ float g_feat2[(size_t)MAXN * HID];

// ---- packed f32x2 helpers (Blackwell FFMA2) ----
__device__ __forceinline__ unsigned long long dupf2(float a) {
    unsigned long long r;
    asm("mov.b64 %0, {%1, %1};" : "=l"(r) : "f"(a));
    return r;
}
__device__ __forceinline__ unsigned long long ffma2(unsigned long long a,
                                                    unsigned long long b,
                                                    unsigned long long c) {
    unsigned long long d;
    asm("fma.rn.f32x2 %0, %1, %2, %3;" : "=l"(d) : "l"(a), "l"(b), "l"(c));
    return d;
}
__device__ __forceinline__ float2 unpackf2(unsigned long long v) {
    float lo, hi;
    asm("mov.b64 {%0, %1}, %2;" : "=f"(lo), "=f"(hi) : "l"(v));
    return make_float2(lo, hi);
}

// Degree count; atomic return value = edge's rank within its dst bucket.
__global__ void k_deg(const int* __restrict__ ei, int E) {
    int e = blockIdx.x * blockDim.x + threadIdx.x;
    if (e < E) g_rank[e] = atomicAdd(&g_deg[ei[(size_t)E + e]], 1);
}

// Pass 1: per-block inclusive scan of deg (+ dinv)
__global__ void k_scan1(int n) {
    __shared__ int s[SCAN_B];
    int i = blockIdx.x * SCAN_B + threadIdx.x;
    int v = (i < n) ? g_deg[i] : 0;
    if (i < n) g_dinv[i] = rsqrtf((float)(v + 1));   // +1 self-loop
    s[threadIdx.x] = v;
    __syncthreads();
#pragma unroll
    for (int o = 1; o < SCAN_B; o <<= 1) {
        int t = 0;
        if (threadIdx.x >= o) t = s[threadIdx.x - o];
        __syncthreads();
        s[threadIdx.x] += t;
        __syncthreads();
    }
    if (i < n) g_incl[i] = s[threadIdx.x];
    if (threadIdx.x == SCAN_B - 1) g_bsum[blockIdx.x] = s[SCAN_B - 1];
}

// Pass 2 (fused): each block reduces bsum[0..bid) itself, then writes rowptr.
__global__ void k_finalize(int n) {
    __shared__ int red[256];
    int bid = blockIdx.x;
    int t = threadIdx.x;
    int p = 0;
    if (t < bid) p = g_bsum[t];
    if (t + 256 < bid) p += g_bsum[t + 256];
    red[t] = p;
    __syncthreads();
#pragma unroll
    for (int o = 128; o > 0; o >>= 1) {
        if (t < o) red[t] += red[t + o];
        __syncthreads();
    }
    int boff = red[0];
    int i = bid * 256 + t;
    if (i < n) {
        g_rowptr[i + 1] = g_incl[i] + boff;
        if (i == 0) g_rowptr[0] = 0;
    }
}

// Atomic-free fill: pos = rowptr[dst] + rank
__global__ void k_fill(const int* __restrict__ ei, int E) {
    int e = blockIdx.x * blockDim.x + threadIdx.x;
    if (e >= E) return;
    int d = ei[(size_t)E + e];
    g_csrc[g_rowptr[d] + g_rank[e]] = ei[e];
}

// GEMM1: g_feat1 = dinv ⊙ (x @ W1). Double-buffered, FFMA2 inner loop.
__global__ __launch_bounds__(256) void k_gemm1(const float* __restrict__ x,
                                               const float* __restrict__ W,
                                               int N) {
    __shared__ float As[2][128][33];
    __shared__ float Bs[2][32][64];
    int t = threadIdx.x;
    int row0 = blockIdx.x * 128;
    int rr = (t >> 4) * 8;
    int cc = (t & 15) * 4;
    unsigned long long acc0[8], acc1[8];   // acc0[i]=(cols cc,cc+1), acc1[i]=(cc+2,cc+3)
#pragma unroll
    for (int i = 0; i < 8; i++) { acc0[i] = 0ULL; acc1[i] = 0ULL; }

    float4 pa[4], pb[2];

#define LDG_CHUNK(kc)                                                          \
    {                                                                          \
        _Pragma("unroll")                                                      \
        for (int j = 0; j < 4; j++) {                                          \
            int id = t + 256 * j;                                              \
            int r = id >> 3, k4 = id & 7;                                      \
            int grow = row0 + r;                                               \
            pa[j] = make_float4(0.f, 0.f, 0.f, 0.f);                           \
            if (grow < N)                                                      \
                pa[j] = *(const float4*)(x + (size_t)grow * INC + (kc) + k4 * 4); \
        }                                                                      \
        _Pragma("unroll")                                                      \
        for (int j = 0; j < 2; j++) {                                          \
            int id = t + 256 * j;                                              \
            int k = id >> 4, c4 = id & 15;                                     \
            pb[j] = *(const float4*)(W + (size_t)((kc) + k) * HID + c4 * 4);   \
        }                                                                      \
    }

#define STS_CHUNK(buf)                                                         \
    {                                                                          \
        _Pragma("unroll")                                                      \
        for (int j = 0; j < 4; j++) {                                          \
            int id = t + 256 * j;                                              \
            int r = id >> 3, k4 = id & 7;                                      \
            As[buf][r][k4 * 4 + 0] = pa[j].x; As[buf][r][k4 * 4 + 1] = pa[j].y; \
            As[buf][r][k4 * 4 + 2] = pa[j].z; As[buf][r][k4 * 4 + 3] = pa[j].w; \
        }                                                                      \
        _Pragma("unroll")                                                      \
        for (int j = 0; j < 2; j++) {                                          \
            int id = t + 256 * j;                                              \
            int k = id >> 4, c4 = id & 15;                                     \
            *(float4*)(&Bs[buf][k][c4 * 4]) = pb[j];                           \
        }                                                                      \
    }

    LDG_CHUNK(0);
    STS_CHUNK(0);
    __syncthreads();

#pragma unroll
    for (int kc = 0; kc < 4; kc++) {
        int cur = kc & 1;
        if (kc < 3) LDG_CHUNK((kc + 1) * 32);
#pragma unroll
        for (int k = 0; k < 32; k++) {
            ulonglong2 bq = *(const ulonglong2*)(&Bs[cur][k][cc]);
#pragma unroll
            for (int i = 0; i < 8; i++) {
                unsigned long long a2 = dupf2(As[cur][rr + i][k]);
                acc0[i] = ffma2(a2, bq.x, acc0[i]);
                acc1[i] = ffma2(a2, bq.y, acc1[i]);
            }
        }
        if (kc < 3) STS_CHUNK(cur ^ 1);
        __syncthreads();
    }
#undef LDG_CHUNK
#undef STS_CHUNK

#pragma unroll
    for (int i = 0; i < 8; i++) {
        int grow = row0 + rr + i;
        if (grow < N) {
            float s = g_dinv[grow];
            float2 lo = unpackf2(acc0[i]);
            float2 hi = unpackf2(acc1[i]);
            float4 o = make_float4(lo.x * s, lo.y * s, hi.x * s, hi.y * s);
            *(float4*)(g_feat1 + (size_t)grow * HID + cc) = o;
        }
    }
}

// Layer-1 aggregate: g_agg1[v] = feat1[v] + sum_{src} feat1[src]
__global__ __launch_bounds__(256) void k_aggregate1(int N) {
    int gtid = blockIdx.x * blockDim.x + threadIdx.x;
    int v = gtid >> 5;
    if (v >= N) return;
    int lane = threadIdx.x & 31;
    int beg = g_rowptr[v];
    int end = g_rowptr[v + 1];

    float2 acc = *(const float2*)(g_feat1 + (size_t)v * HID + lane * 2);

    for (int b = beg; b < end; b += 32) {
        int n = end - b;
        if (n > 32) n = 32;
        int s = (lane < n) ? g_csrc[b + lane] : 0;
#pragma unroll 4
        for (int j = 0; j < n; j++) {
            int sj = __shfl_sync(0xffffffffu, s, j);
            float2 w = *(const float2*)(g_feat1 + (size_t)sj * HID + lane * 2);
            acc.x += w.x;
            acc.y += w.y;
        }
    }
    *(float2*)(g_agg1 + (size_t)v * HID + lane * 2) = acc;
}

// GEMM2: h1 = relu(dinv ⊙ agg1 + b1);  g_feat2 = dinv ⊙ (h1 @ W2). FFMA2 inner loop.
__global__ __launch_bounds__(256) void k_gemm2(const float* __restrict__ W,
                                               const float* __restrict__ b1,
                                               int N) {
    __shared__ float As[2][128][33];
    __shared__ float Bs[2][32][64];
    int t = threadIdx.x;
    int row0 = blockIdx.x * 128;
    int rr = (t >> 4) * 8;
    int cc = (t & 15) * 4;
    unsigned long long acc0[8], acc1[8];
#pragma unroll
    for (int i = 0; i < 8; i++) { acc0[i] = 0ULL; acc1[i] = 0ULL; }

    float4 pa[4], pb[2];

#define LDG_CHUNK2(kc)                                                          \
    {                                                                           \
        _Pragma("unroll")                                                       \
        for (int j = 0; j < 4; j++) {                                           \
            int id = t + 256 * j;                                               \
            int r = id >> 3, k4 = id & 7;                                       \
            int grow = row0 + r;                                                \
            pa[j] = make_float4(0.f, 0.f, 0.f, 0.f);                            \
            if (grow < N) {                                                     \
                float4 v = *(const float4*)(g_agg1 + (size_t)grow * HID + (kc) + k4 * 4); \
                float dv = g_dinv[grow];                                        \
                pa[j].x = fmaxf(fmaf(v.x, dv, __ldg(b1 + (kc) + k4 * 4 + 0)), 0.f); \
                pa[j].y = fmaxf(fmaf(v.y, dv, __ldg(b1 + (kc) + k4 * 4 + 1)), 0.f); \
                pa[j].z = fmaxf(fmaf(v.z, dv, __ldg(b1 + (kc) + k4 * 4 + 2)), 0.f); \
                pa[j].w = fmaxf(fmaf(v.w, dv, __ldg(b1 + (kc) + k4 * 4 + 3)), 0.f); \
            }                                                                   \
        }                                                                       \
        _Pragma("unroll")                                                       \
        for (int j = 0; j < 2; j++) {                                           \
            int id = t + 256 * j;                                               \
            int k = id >> 4, c4 = id & 15;                                      \
            pb[j] = *(const float4*)(W + (size_t)((kc) + k) * HID + c4 * 4);    \
        }                                                                       \
    }

#define STS_CHUNK2(buf)                                                         \
    {                                                                           \
        _Pragma("unroll")                                                       \
        for (int j = 0; j < 4; j++) {                                           \
            int id = t + 256 * j;                                               \
            int r = id >> 3, k4 = id & 7;                                       \
            As[buf][r][k4 * 4 + 0] = pa[j].x; As[buf][r][k4 * 4 + 1] = pa[j].y; \
            As[buf][r][k4 * 4 + 2] = pa[j].z; As[buf][r][k4 * 4 + 3] = pa[j].w; \
        }                                                                       \
        _Pragma("unroll")                                                       \
        for (int j = 0; j < 2; j++) {                                           \
            int id = t + 256 * j;                                               \
            int k = id >> 4, c4 = id & 15;                                      \
            *(float4*)(&Bs[buf][k][c4 * 4]) = pb[j];                            \
        }                                                                       \
    }

    LDG_CHUNK2(0);
    STS_CHUNK2(0);
    __syncthreads();

#pragma unroll
    for (int kc = 0; kc < 2; kc++) {
        int cur = kc & 1;
        if (kc < 1) LDG_CHUNK2(32);
#pragma unroll
        for (int k = 0; k < 32; k++) {
            ulonglong2 bq = *(const ulonglong2*)(&Bs[cur][k][cc]);
#pragma unroll
            for (int i = 0; i < 8; i++) {
                unsigned long long a2 = dupf2(As[cur][rr + i][k]);
                acc0[i] = ffma2(a2, bq.x, acc0[i]);
                acc1[i] = ffma2(a2, bq.y, acc1[i]);
            }
        }
        if (kc < 1) STS_CHUNK2(cur ^ 1);
        __syncthreads();
    }
#undef LDG_CHUNK2
#undef STS_CHUNK2

#pragma unroll
    for (int i = 0; i < 8; i++) {
        int grow = row0 + rr + i;
        if (grow < N) {
            float s = g_dinv[grow];
            float2 lo = unpackf2(acc0[i]);
            float2 hi = unpackf2(acc1[i]);
            float4 o = make_float4(lo.x * s, lo.y * s, hi.x * s, hi.y * s);
            *(float4*)(g_feat2 + (size_t)grow * HID + cc) = o;
        }
    }
}

// Layer-2 aggregate FUSED with classifier.
__global__ __launch_bounds__(256) void k_agg_out(const float* __restrict__ b2,
                                                 const float* __restrict__ Wc,
                                                 const float* __restrict__ bc,
                                                 float* __restrict__ out, int N) {
    int gtid = blockIdx.x * blockDim.x + threadIdx.x;
    int v = gtid >> 5;
    if (v >= N) return;
    int lane = threadIdx.x & 31;
    int beg = g_rowptr[v];
    int end = g_rowptr[v + 1];

    float2 acc = *(const float2*)(g_feat2 + (size_t)v * HID + lane * 2);

    for (int b = beg; b < end; b += 32) {
        int n = end - b;
        if (n > 32) n = 32;
        int s = (lane < n) ? g_csrc[b + lane] : 0;
#pragma unroll 4
        for (int j = 0; j < n; j++) {
            int sj = __shfl_sync(0xffffffffu, s, j);
            float2 w = *(const float2*)(g_feat2 + (size_t)sj * HID + lane * 2);
            acc.x += w.x;
            acc.y += w.y;
        }
    }
    float dv = g_dinv[v];
    float h0 = fmaxf(fmaf(acc.x, dv, __ldg(b2 + lane * 2 + 0)), 0.f);
    float h1 = fmaxf(fmaf(acc.y, dv, __ldg(b2 + lane * 2 + 1)), 0.f);
    float p = h0 * __ldg(Wc + lane * 2) + h1 * __ldg(Wc + lane * 2 + 1);
#pragma unroll
    for (int o = 16; o > 0; o >>= 1) p += __shfl_down_sync(0xffffffffu, p, o);
    if (lane == 0) out[v] = p + __ldg(bc);
}

extern "C" void kernel_launch(void* const* d_in, const int* in_sizes, int n_in,
                              void* d_out, int out_size) {
    const float* x  = (const float*)d_in[0];
    const int*   ei = (const int*)d_in[1];
    const float* W1 = (const float*)d_in[2];
    const float* b1 = (const float*)d_in[3];
    const float* W2 = (const float*)d_in[4];
    const float* b2 = (const float*)d_in[5];
    const float* Wc = (const float*)d_in[6];
    const float* bc = (const float*)d_in[7];
    float* out = (float*)d_out;

    int N = in_sizes[0] / INC;
    int E = in_sizes[1] / 2;
    int nb = (N + SCAN_B - 1) / SCAN_B;

    // CSR build + dinv
    void* degp = 0;
    cudaGetSymbolAddress(&degp, g_deg);
    cudaMemsetAsync(degp, 0, (size_t)N * sizeof(int));
    k_deg<<<(E + 255) / 256, 256>>>(ei, E);
    k_scan1<<<nb, SCAN_B>>>(N);
    k_finalize<<<nb, 256>>>(N);
    k_fill<<<(E + 255) / 256, 256>>>(ei, E);

    // Layer 1
    k_gemm1<<<(N + 127) / 128, 256>>>(x, W1, N);
    k_aggregate1<<<(N * 32 + 255) / 256, 256>>>(N);

    // Layer 2 (+ fused classifier)
    k_gemm2<<<(N + 127) / 128, 256>>>(W2, b1, N);
    k_agg_out<<<(N * 32 + 255) / 256, 256>>>(b2, Wc, bc, out, N);
}

// round 10
// speedup vs baseline: 1.2178x; 1.0041x over previous
#include <cuda_runtime.h>
#include <math.h>

#define INC 128
#define HID 64
#define MAXN 100000
#define MAXE 1600000
#define SCAN_B 256

__device__ int   g_deg [MAXN];
__device__ int   g_incl[MAXN];
__device__ int   g_bsum[512];
__device__ int   g_rowptr[MAXN + 1];
__device__ int   g_rank[MAXE];
__device__ int   g_csrc[MAXE];
__device__ float g_dinv[MAXN];
__device__ float g_feat1[(size_t)MAXN * HID];   // UNSCALED h = x@W1
__device__ float g_agg1 [(size_t)MAXN * HID];
__device__ float g_feat2[(size_t)MAXN * HID];

// ---- packed f32x2 helpers (Blackwell FFMA2) ----
__device__ __forceinline__ unsigned long long dupf2(float a) {
    unsigned long long r;
    asm("mov.b64 %0, {%1, %1};" : "=l"(r) : "f"(a));
    return r;
}
__device__ __forceinline__ unsigned long long ffma2(unsigned long long a,
                                                    unsigned long long b,
                                                    unsigned long long c) {
    unsigned long long d;
    asm("fma.rn.f32x2 %0, %1, %2, %3;" : "=l"(d) : "l"(a), "l"(b), "l"(c));
    return d;
}
__device__ __forceinline__ float2 unpackf2(unsigned long long v) {
    float lo, hi;
    asm("mov.b64 {%0, %1}, %2;" : "=f"(lo), "=f"(hi) : "l"(v));
    return make_float2(lo, hi);
}

// Degree count; atomic return value = edge's rank within its dst bucket.
__global__ void k_deg(const int* __restrict__ ei, int E) {
    int e = blockIdx.x * blockDim.x + threadIdx.x;
    if (e < E) g_rank[e] = atomicAdd(&g_deg[ei[(size_t)E + e]], 1);
}

// Pass 1: per-block inclusive scan of deg (+ dinv)
__global__ void k_scan1(int n) {
    __shared__ int s[SCAN_B];
    int i = blockIdx.x * SCAN_B + threadIdx.x;
    int v = (i < n) ? g_deg[i] : 0;
    if (i < n) g_dinv[i] = rsqrtf((float)(v + 1));   // +1 self-loop
    s[threadIdx.x] = v;
    __syncthreads();
#pragma unroll
    for (int o = 1; o < SCAN_B; o <<= 1) {
        int t = 0;
        if (threadIdx.x >= o) t = s[threadIdx.x - o];
        __syncthreads();
        s[threadIdx.x] += t;
        __syncthreads();
    }
    if (i < n) g_incl[i] = s[threadIdx.x];
    if (threadIdx.x == SCAN_B - 1) g_bsum[blockIdx.x] = s[SCAN_B - 1];
}

// Pass 2 (fused): each block reduces bsum[0..bid) itself, then writes rowptr.
__global__ void k_finalize(int n) {
    __shared__ int red[256];
    int bid = blockIdx.x;
    int t = threadIdx.x;
    int p = 0;
    if (t < bid) p = g_bsum[t];
    if (t + 256 < bid) p += g_bsum[t + 256];
    red[t] = p;
    __syncthreads();
#pragma unroll
    for (int o = 128; o > 0; o >>= 1) {
        if (t < o) red[t] += red[t + o];
        __syncthreads();
    }
    int boff = red[0];
    int i = bid * 256 + t;
    if (i < n) {
        g_rowptr[i + 1] = g_incl[i] + boff;
        if (i == 0) g_rowptr[0] = 0;
    }
}

// Atomic-free fill: pos = rowptr[dst] + rank
__global__ void k_fill(const int* __restrict__ ei, int E) {
    int e = blockIdx.x * blockDim.x + threadIdx.x;
    if (e >= E) return;
    int d = ei[(size_t)E + e];
    g_csrc[g_rowptr[d] + g_rank[e]] = ei[e];
}

// GEMM1: g_feat1 = x @ W1 (UNSCALED — no dinv dependency, runs concurrent with CSR build)
__global__ __launch_bounds__(256) void k_gemm1(const float* __restrict__ x,
                                               const float* __restrict__ W,
                                               int N) {
    __shared__ float As[2][128][33];
    __shared__ float Bs[2][32][64];
    int t = threadIdx.x;
    int row0 = blockIdx.x * 128;
    int rr = (t >> 4) * 8;
    int cc = (t & 15) * 4;
    unsigned long long acc0[8], acc1[8];
#pragma unroll
    for (int i = 0; i < 8; i++) { acc0[i] = 0ULL; acc1[i] = 0ULL; }

    float4 pa[4], pb[2];

#define LDG_CHUNK(kc)                                                          \
    {                                                                          \
        _Pragma("unroll")                                                      \
        for (int j = 0; j < 4; j++) {                                          \
            int id = t + 256 * j;                                              \
            int r = id >> 3, k4 = id & 7;                                      \
            int grow = row0 + r;                                               \
            pa[j] = make_float4(0.f, 0.f, 0.f, 0.f);                           \
            if (grow < N)                                                      \
                pa[j] = *(const float4*)(x + (size_t)grow * INC + (kc) + k4 * 4); \
        }                                                                      \
        _Pragma("unroll")                                                      \
        for (int j = 0; j < 2; j++) {                                          \
            int id = t + 256 * j;                                              \
            int k = id >> 4, c4 = id & 15;                                     \
            pb[j] = *(const float4*)(W + (size_t)((kc) + k) * HID + c4 * 4);   \
        }                                                                      \
    }

#define STS_CHUNK(buf)                                                         \
    {                                                                          \
        _Pragma("unroll")                                                      \
        for (int j = 0; j < 4; j++) {                                          \
            int id = t + 256 * j;                                              \
            int r = id >> 3, k4 = id & 7;                                      \
            As[buf][r][k4 * 4 + 0] = pa[j].x; As[buf][r][k4 * 4 + 1] = pa[j].y; \
            As[buf][r][k4 * 4 + 2] = pa[j].z; As[buf][r][k4 * 4 + 3] = pa[j].w; \
        }                                                                      \
        _Pragma("unroll")                                                      \
        for (int j = 0; j < 2; j++) {                                          \
            int id = t + 256 * j;                                              \
            int k = id >> 4, c4 = id & 15;                                     \
            *(float4*)(&Bs[buf][k][c4 * 4]) = pb[j];                           \
        }                                                                      \
    }

    LDG_CHUNK(0);
    STS_CHUNK(0);
    __syncthreads();

#pragma unroll
    for (int kc = 0; kc < 4; kc++) {
        int cur = kc & 1;
        if (kc < 3) LDG_CHUNK((kc + 1) * 32);
#pragma unroll
        for (int k = 0; k < 32; k++) {
            ulonglong2 bq = *(const ulonglong2*)(&Bs[cur][k][cc]);
#pragma unroll
            for (int i = 0; i < 8; i++) {
                unsigned long long a2 = dupf2(As[cur][rr + i][k]);
                acc0[i] = ffma2(a2, bq.x, acc0[i]);
                acc1[i] = ffma2(a2, bq.y, acc1[i]);
            }
        }
        if (kc < 3) STS_CHUNK(cur ^ 1);
        __syncthreads();
    }
#undef LDG_CHUNK
#undef STS_CHUNK

#pragma unroll
    for (int i = 0; i < 8; i++) {
        int grow = row0 + rr + i;
        if (grow < N) {
            float2 lo = unpackf2(acc0[i]);
            float2 hi = unpackf2(acc1[i]);
            *(float4*)(g_feat1 + (size_t)grow * HID + cc) =
                make_float4(lo.x, lo.y, hi.x, hi.y);
        }
    }
}

// Layer-1 aggregate with per-source scaling:
// g_agg1[v] = dinv[v]*h[v] + sum_{src} dinv[src]*h[src]
__global__ __launch_bounds__(256) void k_aggregate1(int N) {
    int gtid = blockIdx.x * blockDim.x + threadIdx.x;
    int v = gtid >> 5;
    if (v >= N) return;
    int lane = threadIdx.x & 31;
    int beg = g_rowptr[v];
    int end = g_rowptr[v + 1];

    float dv = g_dinv[v];
    float2 self = *(const float2*)(g_feat1 + (size_t)v * HID + lane * 2);
    float2 acc = make_float2(self.x * dv, self.y * dv);

    for (int b = beg; b < end; b += 32) {
        int n = end - b;
        if (n > 32) n = 32;
        int s = 0; float f = 0.f;
        if (lane < n) { s = g_csrc[b + lane]; f = g_dinv[s]; }
#pragma unroll 4
        for (int j = 0; j < n; j++) {
            int sj = __shfl_sync(0xffffffffu, s, j);
            float fj = __shfl_sync(0xffffffffu, f, j);
            float2 w = *(const float2*)(g_feat1 + (size_t)sj * HID + lane * 2);
            acc.x = fmaf(fj, w.x, acc.x);
            acc.y = fmaf(fj, w.y, acc.y);
        }
    }
    *(float2*)(g_agg1 + (size_t)v * HID + lane * 2) = acc;
}

// GEMM2: h1 = relu(dinv ⊙ agg1 + b1);  g_feat2 = dinv ⊙ (h1 @ W2). FFMA2 inner loop.
__global__ __launch_bounds__(256) void k_gemm2(const float* __restrict__ W,
                                               const float* __restrict__ b1,
                                               int N) {
    __shared__ float As[2][128][33];
    __shared__ float Bs[2][32][64];
    int t = threadIdx.x;
    int row0 = blockIdx.x * 128;
    int rr = (t >> 4) * 8;
    int cc = (t & 15) * 4;
    unsigned long long acc0[8], acc1[8];
#pragma unroll
    for (int i = 0; i < 8; i++) { acc0[i] = 0ULL; acc1[i] = 0ULL; }

    float4 pa[4], pb[2];

#define LDG_CHUNK2(kc)                                                          \
    {                                                                           \
        _Pragma("unroll")                                                       \
        for (int j = 0; j < 4; j++) {                                           \
            int id = t + 256 * j;                                               \
            int r = id >> 3, k4 = id & 7;                                       \
            int grow = row0 + r;                                                \
            pa[j] = make_float4(0.f, 0.f, 0.f, 0.f);                            \
            if (grow < N) {                                                     \
                float4 v = *(const float4*)(g_agg1 + (size_t)grow * HID + (kc) + k4 * 4); \
                float dv = g_dinv[grow];                                        \
                pa[j].x = fmaxf(fmaf(v.x, dv, __ldg(b1 + (kc) + k4 * 4 + 0)), 0.f); \
                pa[j].y = fmaxf(fmaf(v.y, dv, __ldg(b1 + (kc) + k4 * 4 + 1)), 0.f); \
                pa[j].z = fmaxf(fmaf(v.z, dv, __ldg(b1 + (kc) + k4 * 4 + 2)), 0.f); \
                pa[j].w = fmaxf(fmaf(v.w, dv, __ldg(b1 + (kc) + k4 * 4 + 3)), 0.f); \
            }                                                                   \
        }                                                                       \
        _Pragma("unroll")                                                       \
        for (int j = 0; j < 2; j++) {                                           \
            int id = t + 256 * j;                                               \
            int k = id >> 4, c4 = id & 15;                                      \
            pb[j] = *(const float4*)(W + (size_t)((kc) + k) * HID + c4 * 4);    \
        }                                                                       \
    }

#define STS_CHUNK2(buf)                                                         \
    {                                                                           \
        _Pragma("unroll")                                                       \
        for (int j = 0; j < 4; j++) {                                           \
            int id = t + 256 * j;                                               \
            int r = id >> 3, k4 = id & 7;                                       \
            As[buf][r][k4 * 4 + 0] = pa[j].x; As[buf][r][k4 * 4 + 1] = pa[j].y; \
            As[buf][r][k4 * 4 + 2] = pa[j].z; As[buf][r][k4 * 4 + 3] = pa[j].w; \
        }                                                                       \
        _Pragma("unroll")                                                       \
        for (int j = 0; j < 2; j++) {                                           \
            int id = t + 256 * j;                                               \
            int k = id >> 4, c4 = id & 15;                                      \
            *(float4*)(&Bs[buf][k][c4 * 4]) = pb[j];                            \
        }                                                                       \
    }

    LDG_CHUNK2(0);
    STS_CHUNK2(0);
    __syncthreads();

#pragma unroll
    for (int kc = 0; kc < 2; kc++) {
        int cur = kc & 1;
        if (kc < 1) LDG_CHUNK2(32);
#pragma unroll
        for (int k = 0; k < 32; k++) {
            ulonglong2 bq = *(const ulonglong2*)(&Bs[cur][k][cc]);
#pragma unroll
            for (int i = 0; i < 8; i++) {
                unsigned long long a2 = dupf2(As[cur][rr + i][k]);
                acc0[i] = ffma2(a2, bq.x, acc0[i]);
                acc1[i] = ffma2(a2, bq.y, acc1[i]);
            }
        }
        if (kc < 1) STS_CHUNK2(cur ^ 1);
        __syncthreads();
    }
#undef LDG_CHUNK2
#undef STS_CHUNK2

#pragma unroll
    for (int i = 0; i < 8; i++) {
        int grow = row0 + rr + i;
        if (grow < N) {
            float s = g_dinv[grow];
            float2 lo = unpackf2(acc0[i]);
            float2 hi = unpackf2(acc1[i]);
            float4 o = make_float4(lo.x * s, lo.y * s, hi.x * s, hi.y * s);
            *(float4*)(g_feat2 + (size_t)grow * HID + cc) = o;
        }
    }
}

// Layer-2 aggregate FUSED with classifier. (feat2 already dinv-scaled.)
__global__ __launch_bounds__(256) void k_agg_out(const float* __restrict__ b2,
                                                 const float* __restrict__ Wc,
                                                 const float* __restrict__ bc,
                                                 float* __restrict__ out, int N) {
    int gtid = blockIdx.x * blockDim.x + threadIdx.x;
    int v = gtid >> 5;
    if (v >= N) return;
    int lane = threadIdx.x & 31;
    int beg = g_rowptr[v];
    int end = g_rowptr[v + 1];

    float2 acc = *(const float2*)(g_feat2 + (size_t)v * HID + lane * 2);

    for (int b = beg; b < end; b += 32) {
        int n = end - b;
        if (n > 32) n = 32;
        int s = (lane < n) ? g_csrc[b + lane] : 0;
#pragma unroll 4
        for (int j = 0; j < n; j++) {
            int sj = __shfl_sync(0xffffffffu, s, j);
            float2 w = *(const float2*)(g_feat2 + (size_t)sj * HID + lane * 2);
            acc.x += w.x;
            acc.y += w.y;
        }
    }
    float dv = g_dinv[v];
    float h0 = fmaxf(fmaf(acc.x, dv, __ldg(b2 + lane * 2 + 0)), 0.f);
    float h1 = fmaxf(fmaf(acc.y, dv, __ldg(b2 + lane * 2 + 1)), 0.f);
    float p = h0 * __ldg(Wc + lane * 2) + h1 * __ldg(Wc + lane * 2 + 1);
#pragma unroll
    for (int o = 16; o > 0; o >>= 1) p += __shfl_down_sync(0xffffffffu, p, o);
    if (lane == 0) out[v] = p + __ldg(bc);
}

extern "C" void kernel_launch(void* const* d_in, const int* in_sizes, int n_in,
                              void* d_out, int out_size) {
    const float* x  = (const float*)d_in[0];
    const int*   ei = (const int*)d_in[1];
    const float* W1 = (const float*)d_in[2];
    const float* b1 = (const float*)d_in[3];
    const float* W2 = (const float*)d_in[4];
    const float* b2 = (const float*)d_in[5];
    const float* Wc = (const float*)d_in[6];
    const float* bc = (const float*)d_in[7];
    float* out = (float*)d_out;

    int N = in_sizes[0] / INC;
    int E = in_sizes[1] / 2;
    int nb = (N + SCAN_B - 1) / SCAN_B;

    // Side stream + fork/join events, created once (first call = correctness run,
    // so the captured call performs no resource create/destroy).
    static cudaStream_t s2 = [] {
        cudaStream_t s; cudaStreamCreateWithFlags(&s, cudaStreamNonBlocking); return s;
    }();
    static cudaEvent_t evFork = [] {
        cudaEvent_t e; cudaEventCreateWithFlags(&e, cudaEventDisableTiming); return e;
    }();
    static cudaEvent_t evJoin = [] {
        cudaEvent_t e; cudaEventCreateWithFlags(&e, cudaEventDisableTiming); return e;
    }();

    void* degp = 0;
    cudaGetSymbolAddress(&degp, g_deg);

    // Fork: CSR build on s2, concurrent with gemm1 on the main stream.
    cudaEventRecord(evFork, 0);
    cudaStreamWaitEvent(s2, evFork, 0);
    cudaMemsetAsync(degp, 0, (size_t)N * sizeof(int), s2);
    k_deg<<<(E + 255) / 256, 256, 0, s2>>>(ei, E);
    k_scan1<<<nb, SCAN_B, 0, s2>>>(N);
    k_finalize<<<nb, 256, 0, s2>>>(N);
    k_fill<<<(E + 255) / 256, 256, 0, s2>>>(ei, E);
    cudaEventRecord(evJoin, s2);

    // Main stream: layer-1 GEMM (no dinv dependency).
    k_gemm1<<<(N + 127) / 128, 256>>>(x, W1, N);

    // Join, then the serial tail.
    cudaStreamWaitEvent(0, evJoin, 0);
    k_aggregate1<<<(N * 32 + 255) / 256, 256>>>(N);
    k_gemm2<<<(N + 127) / 128, 256>>>(W2, b1, N);
    k_agg_out<<<(N * 32 + 255) / 256, 256>>>(b2, Wc, bc, out, N);
}

// round 11
// speedup vs baseline: 1.2799x; 1.0510x over previous
#include <cuda_runtime.h>
#include <cuda_fp16.h>
#include <math.h>

#define INC 128
#define HID 64
#define MAXN 100000
#define MAXE 1600000
#define SCAN_B 256

__device__ int    g_deg [MAXN];
__device__ int    g_incl[MAXN];
__device__ int    g_bsum[512];
__device__ int    g_rowptr[MAXN + 1];
__device__ int    g_rank[MAXE];
__device__ int    g_csrc[MAXE];
__device__ float  g_dinv[MAXN];
__device__ __half g_feat1h[(size_t)MAXN * HID];   // UNSCALED h = x@W1, fp16 messages
__device__ float  g_agg1 [(size_t)MAXN * HID];
__device__ __half g_feat2h[(size_t)MAXN * HID];   // dinv ⊙ (h1@W2), fp16 messages

// ---- packed f32x2 helpers (Blackwell FFMA2) ----
__device__ __forceinline__ unsigned long long dupf2(float a) {
    unsigned long long r;
    asm("mov.b64 %0, {%1, %1};" : "=l"(r) : "f"(a));
    return r;
}
__device__ __forceinline__ unsigned long long ffma2(unsigned long long a,
                                                    unsigned long long b,
                                                    unsigned long long c) {
    unsigned long long d;
    asm("fma.rn.f32x2 %0, %1, %2, %3;" : "=l"(d) : "l"(a), "l"(b), "l"(c));
    return d;
}
__device__ __forceinline__ float2 unpackf2(unsigned long long v) {
    float lo, hi;
    asm("mov.b64 {%0, %1}, %2;" : "=f"(lo), "=f"(hi) : "l"(v));
    return make_float2(lo, hi);
}

// Degree count; atomic return value = edge's rank within its dst bucket.
__global__ void k_deg(const int* __restrict__ ei, int E) {
    int e = blockIdx.x * blockDim.x + threadIdx.x;
    if (e < E) g_rank[e] = atomicAdd(&g_deg[ei[(size_t)E + e]], 1);
}

// Pass 1: per-block inclusive scan of deg (+ dinv)
__global__ void k_scan1(int n) {
    __shared__ int s[SCAN_B];
    int i = blockIdx.x * SCAN_B + threadIdx.x;
    int v = (i < n) ? g_deg[i] : 0;
    if (i < n) g_dinv[i] = rsqrtf((float)(v + 1));   // +1 self-loop
    s[threadIdx.x] = v;
    __syncthreads();
#pragma unroll
    for (int o = 1; o < SCAN_B; o <<= 1) {
        int t = 0;
        if (threadIdx.x >= o) t = s[threadIdx.x - o];
        __syncthreads();
        s[threadIdx.x] += t;
        __syncthreads();
    }
    if (i < n) g_incl[i] = s[threadIdx.x];
    if (threadIdx.x == SCAN_B - 1) g_bsum[blockIdx.x] = s[SCAN_B - 1];
}

// Pass 2 (fused): each block reduces bsum[0..bid) itself, then writes rowptr.
__global__ void k_finalize(int n) {
    __shared__ int red[256];
    int bid = blockIdx.x;
    int t = threadIdx.x;
    int p = 0;
    if (t < bid) p = g_bsum[t];
    if (t + 256 < bid) p += g_bsum[t + 256];
    red[t] = p;
    __syncthreads();
#pragma unroll
    for (int o = 128; o > 0; o >>= 1) {
        if (t < o) red[t] += red[t + o];
        __syncthreads();
    }
    int boff = red[0];
    int i = bid * 256 + t;
    if (i < n) {
        g_rowptr[i + 1] = g_incl[i] + boff;
        if (i == 0) g_rowptr[0] = 0;
    }
}

// Atomic-free fill: pos = rowptr[dst] + rank
__global__ void k_fill(const int* __restrict__ ei, int E) {
    int e = blockIdx.x * blockDim.x + threadIdx.x;
    if (e >= E) return;
    int d = ei[(size_t)E + e];
    g_csrc[g_rowptr[d] + g_rank[e]] = ei[e];
}

// GEMM1: g_feat1h = fp16(x @ W1)  (unscaled; concurrent with CSR build)
__global__ __launch_bounds__(256) void k_gemm1(const float* __restrict__ x,
                                               const float* __restrict__ W,
                                               int N) {
    __shared__ float As[2][128][33];
    __shared__ float Bs[2][32][64];
    int t = threadIdx.x;
    int row0 = blockIdx.x * 128;
    int rr = (t >> 4) * 8;
    int cc = (t & 15) * 4;
    unsigned long long acc0[8], acc1[8];
#pragma unroll
    for (int i = 0; i < 8; i++) { acc0[i] = 0ULL; acc1[i] = 0ULL; }

    float4 pa[4], pb[2];

#define LDG_CHUNK(kc)                                                          \
    {                                                                          \
        _Pragma("unroll")                                                      \
        for (int j = 0; j < 4; j++) {                                          \
            int id = t + 256 * j;                                              \
            int r = id >> 3, k4 = id & 7;                                      \
            int grow = row0 + r;                                               \
            pa[j] = make_float4(0.f, 0.f, 0.f, 0.f);                           \
            if (grow < N)                                                      \
                pa[j] = *(const float4*)(x + (size_t)grow * INC + (kc) + k4 * 4); \
        }                                                                      \
        _Pragma("unroll")                                                      \
        for (int j = 0; j < 2; j++) {                                          \
            int id = t + 256 * j;                                              \
            int k = id >> 4, c4 = id & 15;                                     \
            pb[j] = *(const float4*)(W + (size_t)((kc) + k) * HID + c4 * 4);   \
        }                                                                      \
    }

#define STS_CHUNK(buf)                                                         \
    {                                                                          \
        _Pragma("unroll")                                                      \
        for (int j = 0; j < 4; j++) {                                          \
            int id = t + 256 * j;                                              \
            int r = id >> 3, k4 = id & 7;                                      \
            As[buf][r][k4 * 4 + 0] = pa[j].x; As[buf][r][k4 * 4 + 1] = pa[j].y; \
            As[buf][r][k4 * 4 + 2] = pa[j].z; As[buf][r][k4 * 4 + 3] = pa[j].w; \
        }                                                                      \
        _Pragma("unroll")                                                      \
        for (int j = 0; j < 2; j++) {                                          \
            int id = t + 256 * j;                                              \
            int k = id >> 4, c4 = id & 15;                                     \
            *(float4*)(&Bs[buf][k][c4 * 4]) = pb[j];                           \
        }                                                                      \
    }

    LDG_CHUNK(0);
    STS_CHUNK(0);
    __syncthreads();

#pragma unroll
    for (int kc = 0; kc < 4; kc++) {
        int cur = kc & 1;
        if (kc < 3) LDG_CHUNK((kc + 1) * 32);
#pragma unroll
        for (int k = 0; k < 32; k++) {
            ulonglong2 bq = *(const ulonglong2*)(&Bs[cur][k][cc]);
#pragma unroll
            for (int i = 0; i < 8; i++) {
                unsigned long long a2 = dupf2(As[cur][rr + i][k]);
                acc0[i] = ffma2(a2, bq.x, acc0[i]);
                acc1[i] = ffma2(a2, bq.y, acc1[i]);
            }
        }
        if (kc < 3) STS_CHUNK(cur ^ 1);
        __syncthreads();
    }
#undef LDG_CHUNK
#undef STS_CHUNK

#pragma unroll
    for (int i = 0; i < 8; i++) {
        int grow = row0 + rr + i;
        if (grow < N) {
            float2 lo = unpackf2(acc0[i]);
            float2 hi = unpackf2(acc1[i]);
            __half2 h0 = __floats2half2_rn(lo.x, lo.y);
            __half2 h1 = __floats2half2_rn(hi.x, hi.y);
            uint2 pk = make_uint2(*(unsigned*)&h0, *(unsigned*)&h1);
            *(uint2*)(g_feat1h + (size_t)grow * HID + cc) = pk;
        }
    }
}

// Layer-1 aggregate (fp16 gather, fp32 accumulate):
// g_agg1[v] = dinv[v]*h[v] + sum_{src} dinv[src]*h[src]
__global__ __launch_bounds__(256) void k_aggregate1(int N) {
    int gtid = blockIdx.x * blockDim.x + threadIdx.x;
    int v = gtid >> 5;
    if (v >= N) return;
    int lane = threadIdx.x & 31;
    int beg = g_rowptr[v];
    int end = g_rowptr[v + 1];

    float dv = g_dinv[v];
    float2 self = __half22float2(*((const __half2*)(g_feat1h + (size_t)v * HID) + lane));
    float2 acc = make_float2(self.x * dv, self.y * dv);

    for (int b = beg; b < end; b += 32) {
        int n = end - b;
        if (n > 32) n = 32;
        int s = 0; float f = 0.f;
        if (lane < n) { s = g_csrc[b + lane]; f = g_dinv[s]; }
#pragma unroll 4
        for (int j = 0; j < n; j++) {
            int sj = __shfl_sync(0xffffffffu, s, j);
            float fj = __shfl_sync(0xffffffffu, f, j);
            float2 w = __half22float2(*((const __half2*)(g_feat1h + (size_t)sj * HID) + lane));
            acc.x = fmaf(fj, w.x, acc.x);
            acc.y = fmaf(fj, w.y, acc.y);
        }
    }
    *(float2*)(g_agg1 + (size_t)v * HID + lane * 2) = acc;
}

// GEMM2: h1 = relu(dinv ⊙ agg1 + b1);  g_feat2h = fp16(dinv ⊙ (h1 @ W2))
__global__ __launch_bounds__(256) void k_gemm2(const float* __restrict__ W,
                                               const float* __restrict__ b1,
                                               int N) {
    __shared__ float As[2][128][33];
    __shared__ float Bs[2][32][64];
    int t = threadIdx.x;
    int row0 = blockIdx.x * 128;
    int rr = (t >> 4) * 8;
    int cc = (t & 15) * 4;
    unsigned long long acc0[8], acc1[8];
#pragma unroll
    for (int i = 0; i < 8; i++) { acc0[i] = 0ULL; acc1[i] = 0ULL; }

    float4 pa[4], pb[2];

#define LDG_CHUNK2(kc)                                                          \
    {                                                                           \
        _Pragma("unroll")                                                       \
        for (int j = 0; j < 4; j++) {                                           \
            int id = t + 256 * j;                                               \
            int r = id >> 3, k4 = id & 7;                                       \
            int grow = row0 + r;                                                \
            pa[j] = make_float4(0.f, 0.f, 0.f, 0.f);                            \
            if (grow < N) {                                                     \
                float4 v = *(const float4*)(g_agg1 + (size_t)grow * HID + (kc) + k4 * 4); \
                float dv = g_dinv[grow];                                        \
                pa[j].x = fmaxf(fmaf(v.x, dv, __ldg(b1 + (kc) + k4 * 4 + 0)), 0.f); \
                pa[j].y = fmaxf(fmaf(v.y, dv, __ldg(b1 + (kc) + k4 * 4 + 1)), 0.f); \
                pa[j].z = fmaxf(fmaf(v.z, dv, __ldg(b1 + (kc) + k4 * 4 + 2)), 0.f); \
                pa[j].w = fmaxf(fmaf(v.w, dv, __ldg(b1 + (kc) + k4 * 4 + 3)), 0.f); \
            }                                                                   \
        }                                                                       \
        _Pragma("unroll")                                                       \
        for (int j = 0; j < 2; j++) {                                           \
            int id = t + 256 * j;                                               \
            int k = id >> 4, c4 = id & 15;                                      \
            pb[j] = *(const float4*)(W + (size_t)((kc) + k) * HID + c4 * 4);    \
        }                                                                       \
    }

#define STS_CHUNK2(buf)                                                         \
    {                                                                           \
        _Pragma("unroll")                                                       \
        for (int j = 0; j < 4; j++) {                                           \
            int id = t + 256 * j;                                               \
            int r = id >> 3, k4 = id & 7;                                       \
            As[buf][r][k4 * 4 + 0] = pa[j].x; As[buf][r][k4 * 4 + 1] = pa[j].y; \
            As[buf][r][k4 * 4 + 2] = pa[j].z; As[buf][r][k4 * 4 + 3] = pa[j].w; \
        }                                                                       \
        _Pragma("unroll")                                                       \
        for (int j = 0; j < 2; j++) {                                           \
            int id = t + 256 * j;                                               \
            int k = id >> 4, c4 = id & 15;                                      \
            *(float4*)(&Bs[buf][k][c4 * 4]) = pb[j];                            \
        }                                                                       \
    }

    LDG_CHUNK2(0);
    STS_CHUNK2(0);
    __syncthreads();

#pragma unroll
    for (int kc = 0; kc < 2; kc++) {
        int cur = kc & 1;
        if (kc < 1) LDG_CHUNK2(32);
#pragma unroll
        for (int k = 0; k < 32; k++) {
            ulonglong2 bq = *(const ulonglong2*)(&Bs[cur][k][cc]);
#pragma unroll
            for (int i = 0; i < 8; i++) {
                unsigned long long a2 = dupf2(As[cur][rr + i][k]);
                acc0[i] = ffma2(a2, bq.x, acc0[i]);
                acc1[i] = ffma2(a2, bq.y, acc1[i]);
            }
        }
        if (kc < 1) STS_CHUNK2(cur ^ 1);
        __syncthreads();
    }
#undef LDG_CHUNK2
#undef STS_CHUNK2

#pragma unroll
    for (int i = 0; i < 8; i++) {
        int grow = row0 + rr + i;
        if (grow < N) {
            float s = g_dinv[grow];
            float2 lo = unpackf2(acc0[i]);
            float2 hi = unpackf2(acc1[i]);
            __half2 h0 = __floats2half2_rn(lo.x * s, lo.y * s);
            __half2 h1 = __floats2half2_rn(hi.x * s, hi.y * s);
            uint2 pk = make_uint2(*(unsigned*)&h0, *(unsigned*)&h1);
            *(uint2*)(g_feat2h + (size_t)grow * HID + cc) = pk;
        }
    }
}

// Layer-2 aggregate FUSED with classifier (fp16 gather, fp32 accumulate).
__global__ __launch_bounds__(256) void k_agg_out(const float* __restrict__ b2,
                                                 const float* __restrict__ Wc,
                                                 const float* __restrict__ bc,
                                                 float* __restrict__ out, int N) {
    int gtid = blockIdx.x * blockDim.x + threadIdx.x;
    int v = gtid >> 5;
    if (v >= N) return;
    int lane = threadIdx.x & 31;
    int beg = g_rowptr[v];
    int end = g_rowptr[v + 1];

    float2 acc = __half22float2(*((const __half2*)(g_feat2h + (size_t)v * HID) + lane));

    for (int b = beg; b < end; b += 32) {
        int n = end - b;
        if (n > 32) n = 32;
        int s = (lane < n) ? g_csrc[b + lane] : 0;
#pragma unroll 4
        for (int j = 0; j < n; j++) {
            int sj = __shfl_sync(0xffffffffu, s, j);
            float2 w = __half22float2(*((const __half2*)(g_feat2h + (size_t)sj * HID) + lane));
            acc.x += w.x;
            acc.y += w.y;
        }
    }
    float dv = g_dinv[v];
    float h0 = fmaxf(fmaf(acc.x, dv, __ldg(b2 + lane * 2 + 0)), 0.f);
    float h1 = fmaxf(fmaf(acc.y, dv, __ldg(b2 + lane * 2 + 1)), 0.f);
    float p = h0 * __ldg(Wc + lane * 2) + h1 * __ldg(Wc + lane * 2 + 1);
#pragma unroll
    for (int o = 16; o > 0; o >>= 1) p += __shfl_down_sync(0xffffffffu, p, o);
    if (lane == 0) out[v] = p + __ldg(bc);
}

extern "C" void kernel_launch(void* const* d_in, const int* in_sizes, int n_in,
                              void* d_out, int out_size) {
    const float* x  = (const float*)d_in[0];
    const int*   ei = (const int*)d_in[1];
    const float* W1 = (const float*)d_in[2];
    const float* b1 = (const float*)d_in[3];
    const float* W2 = (const float*)d_in[4];
    const float* b2 = (const float*)d_in[5];
    const float* Wc = (const float*)d_in[6];
    const float* bc = (const float*)d_in[7];
    float* out = (float*)d_out;

    int N = in_sizes[0] / INC;
    int E = in_sizes[1] / 2;
    int nb = (N + SCAN_B - 1) / SCAN_B;

    static cudaStream_t s2 = [] {
        cudaStream_t s; cudaStreamCreateWithFlags(&s, cudaStreamNonBlocking); return s;
    }();
    static cudaEvent_t evFork = [] {
        cudaEvent_t e; cudaEventCreateWithFlags(&e, cudaEventDisableTiming); return e;
    }();
    static cudaEvent_t evJoin = [] {
        cudaEvent_t e; cudaEventCreateWithFlags(&e, cudaEventDisableTiming); return e;
    }();

    void* degp = 0;
    cudaGetSymbolAddress(&degp, g_deg);

    // Fork: CSR build on s2, concurrent with gemm1 on the main stream.
    cudaEventRecord(evFork, 0);
    cudaStreamWaitEvent(s2, evFork, 0);
    cudaMemsetAsync(degp, 0, (size_t)N * sizeof(int), s2);
    k_deg<<<(E + 255) / 256, 256, 0, s2>>>(ei, E);
    k_scan1<<<nb, SCAN_B, 0, s2>>>(N);
    k_finalize<<<nb, 256, 0, s2>>>(N);
    k_fill<<<(E + 255) / 256, 256, 0, s2>>>(ei, E);
    cudaEventRecord(evJoin, s2);

    // Main stream: layer-1 GEMM (no dinv dependency).
    k_gemm1<<<(N + 127) / 128, 256>>>(x, W1, N);

    // Join, then the serial tail.
    cudaStreamWaitEvent(0, evJoin, 0);
    k_aggregate1<<<(N * 32 + 255) / 256, 256>>>(N);
    k_gemm2<<<(N + 127) / 128, 256>>>(W2, b1, N);
    k_agg_out<<<(N * 32 + 255) / 256, 256>>>(b2, Wc, bc, out, N);
}

// round 13
// speedup vs baseline: 1.5373x; 1.2011x over previous
#include <cuda_runtime.h>
#include <cuda_fp16.h>
#include <mma.h>
#include <math.h>

using namespace nvcuda;

#define INC 128
#define HID 64
#define MAXN 100000
#define MAXE 1600000
#define SCAN_B 256

__device__ int    g_deg [MAXN];
__device__ int    g_incl[MAXN];
__device__ int    g_bsum[512];
__device__ int    g_rowptr[MAXN + 1];
__device__ int    g_rank[MAXE];
__device__ int    g_csrc[MAXE];
__device__ float  g_dinv[MAXN];
__device__ __half g_feat1h[(size_t)MAXN * HID];   // UNSCALED h = x@W1 (fp16)
__device__ float  g_agg1 [(size_t)MAXN * HID];
__device__ __half g_feat2h[(size_t)MAXN * HID];   // dinv ⊙ (h1@W2) (fp16)

// Degree count; atomic return value = edge's rank within its dst bucket.
__global__ void k_deg(const int* __restrict__ ei, int E) {
    int e = blockIdx.x * blockDim.x + threadIdx.x;
    if (e < E) g_rank[e] = atomicAdd(&g_deg[ei[(size_t)E + e]], 1);
}

// Pass 1: per-block inclusive scan of deg (+ dinv)
__global__ void k_scan1(int n) {
    __shared__ int s[SCAN_B];
    int i = blockIdx.x * SCAN_B + threadIdx.x;
    int v = (i < n) ? g_deg[i] : 0;
    if (i < n) g_dinv[i] = rsqrtf((float)(v + 1));   // +1 self-loop
    s[threadIdx.x] = v;
    __syncthreads();
#pragma unroll
    for (int o = 1; o < SCAN_B; o <<= 1) {
        int t = 0;
        if (threadIdx.x >= o) t = s[threadIdx.x - o];
        __syncthreads();
        s[threadIdx.x] += t;
        __syncthreads();
    }
    if (i < n) g_incl[i] = s[threadIdx.x];
    if (threadIdx.x == SCAN_B - 1) g_bsum[blockIdx.x] = s[SCAN_B - 1];
}

// Pass 2 (fused): each block reduces bsum[0..bid) itself, then writes rowptr.
__global__ void k_finalize(int n) {
    __shared__ int red[256];
    int bid = blockIdx.x;
    int t = threadIdx.x;
    int p = 0;
    if (t < bid) p = g_bsum[t];
    if (t + 256 < bid) p += g_bsum[t + 256];
    red[t] = p;
    __syncthreads();
#pragma unroll
    for (int o = 128; o > 0; o >>= 1) {
        if (t < o) red[t] += red[t + o];
        __syncthreads();
    }
    int boff = red[0];
    int i = bid * 256 + t;
    if (i < n) {
        g_rowptr[i + 1] = g_incl[i] + boff;
        if (i == 0) g_rowptr[0] = 0;
    }
}

// Atomic-free fill: pos = rowptr[dst] + rank
__global__ void k_fill(const int* __restrict__ ei, int E) {
    int e = blockIdx.x * blockDim.x + threadIdx.x;
    if (e >= E) return;
    int d = ei[(size_t)E + e];
    g_csrc[g_rowptr[d] + g_rank[e]] = ei[e];
}

// GEMM1 (WMMA fp16): g_feat1h = fp16(x @ W1), unscaled.
// CTA = 128 rows x 64 cols, 8 warps (16 rows each), K=128 in two 64-chunks.
__global__ __launch_bounds__(256) void k_gemm1(const float* __restrict__ x,
                                               const float* __restrict__ W,
                                               int N) {
    __shared__ __half As[128][72];       // current K-chunk of A (fp16)
    __shared__ __half Bs[128][72];       // all of W1 (fp16)
    __shared__ float  Ps[8][16][20];     // per-warp epilogue patch
    int t = threadIdx.x;
    int wid = t >> 5, lane = t & 31;
    int row0 = blockIdx.x * 128;

    wmma::fragment<wmma::accumulator, 16, 16, 16, float> acc[4];
#pragma unroll
    for (int n = 0; n < 4; n++) wmma::fill_fragment(acc[n], 0.f);

    // Convert W1 (128x64 fp32) -> Bs fp16, once.
#pragma unroll
    for (int j = 0; j < 8; j++) {
        int id = t + 256 * j;           // 0..2047 (16 float4 per row)
        int kk = id >> 4, q = id & 15;
        float4 v = *(const float4*)(W + (size_t)kk * HID + q * 4);
        *(__half2*)&Bs[kk][q * 4]     = __floats2half2_rn(v.x, v.y);
        *(__half2*)&Bs[kk][q * 4 + 2] = __floats2half2_rn(v.z, v.w);
    }

#pragma unroll
    for (int kc = 0; kc < 2; kc++) {
        // Convert A chunk: rows 0..127, k in [kc*64, kc*64+64)
#pragma unroll
        for (int j = 0; j < 8; j++) {
            int id = t + 256 * j;
            int r = id >> 4, q = id & 15;
            int grow = row0 + r;
            float4 v = make_float4(0.f, 0.f, 0.f, 0.f);
            if (grow < N)
                v = *(const float4*)(x + (size_t)grow * INC + kc * 64 + q * 4);
            *(__half2*)&As[r][q * 4]     = __floats2half2_rn(v.x, v.y);
            *(__half2*)&As[r][q * 4 + 2] = __floats2half2_rn(v.z, v.w);
        }
        __syncthreads();

#pragma unroll
        for (int ks = 0; ks < 4; ks++) {
            wmma::fragment<wmma::matrix_a, 16, 16, 16, __half, wmma::row_major> a;
            wmma::load_matrix_sync(a, &As[wid * 16][ks * 16], 72);
#pragma unroll
            for (int n = 0; n < 4; n++) {
                wmma::fragment<wmma::matrix_b, 16, 16, 16, __half, wmma::row_major> b;
                wmma::load_matrix_sync(b, &Bs[kc * 64 + ks * 16][n * 16], 72);
                wmma::mma_sync(acc[n], a, b, acc[n]);
            }
        }
        __syncthreads();
    }

    // Epilogue: fp32 frags -> fp16 rows (unscaled)
    int r = lane >> 1, c8 = (lane & 1) * 8;
    int grow = row0 + wid * 16 + r;
#pragma unroll
    for (int n = 0; n < 4; n++) {
        wmma::store_matrix_sync(&Ps[wid][0][0], acc[n], 20, wmma::mem_row_major);
        __syncwarp();
        if (grow < N) {
            float4 f0 = *(float4*)&Ps[wid][r][c8];
            float4 f1 = *(float4*)&Ps[wid][r][c8 + 4];
            __half2 h0 = __floats2half2_rn(f0.x, f0.y);
            __half2 h1 = __floats2half2_rn(f0.z, f0.w);
            __half2 h2 = __floats2half2_rn(f1.x, f1.y);
            __half2 h3 = __floats2half2_rn(f1.z, f1.w);
            uint4 pk = make_uint4(*(unsigned*)&h0, *(unsigned*)&h1,
                                  *(unsigned*)&h2, *(unsigned*)&h3);
            *(uint4*)(g_feat1h + (size_t)grow * HID + n * 16 + c8) = pk;
        }
        __syncwarp();
    }
}

// Layer-1 aggregate (fp16 gather, fp32 accumulate):
// g_agg1[v] = dinv[v]*h[v] + sum_{src} dinv[src]*h[src]
__global__ __launch_bounds__(256) void k_aggregate1(int N) {
    int gtid = blockIdx.x * blockDim.x + threadIdx.x;
    int v = gtid >> 5;
    if (v >= N) return;
    int lane = threadIdx.x & 31;
    int beg = g_rowptr[v];
    int end = g_rowptr[v + 1];

    float dv = g_dinv[v];
    float2 self = __half22float2(*((const __half2*)(g_feat1h + (size_t)v * HID) + lane));
    float2 acc = make_float2(self.x * dv, self.y * dv);

    for (int b = beg; b < end; b += 32) {
        int n = end - b;
        if (n > 32) n = 32;
        int s = 0; float f = 0.f;
        if (lane < n) { s = g_csrc[b + lane]; f = g_dinv[s]; }
#pragma unroll 4
        for (int j = 0; j < n; j++) {
            int sj = __shfl_sync(0xffffffffu, s, j);
            float fj = __shfl_sync(0xffffffffu, f, j);
            float2 w = __half22float2(*((const __half2*)(g_feat1h + (size_t)sj * HID) + lane));
            acc.x = fmaf(fj, w.x, acc.x);
            acc.y = fmaf(fj, w.y, acc.y);
        }
    }
    *(float2*)(g_agg1 + (size_t)v * HID + lane * 2) = acc;
}

// GEMM2 (WMMA fp16): h1 = relu(dinv ⊙ agg1 + b1); g_feat2h = fp16(dinv ⊙ (h1 @ W2))
__global__ __launch_bounds__(256) void k_gemm2(const float* __restrict__ W,
                                               const float* __restrict__ b1,
                                               int N) {
    __shared__ __half As[128][72];       // h1 (fp16), K=64
    __shared__ __half Bs[64][72];        // W2 (fp16)
    __shared__ float  Ps[8][16][20];
    int t = threadIdx.x;
    int wid = t >> 5, lane = t & 31;
    int row0 = blockIdx.x * 128;

    wmma::fragment<wmma::accumulator, 16, 16, 16, float> acc[4];
#pragma unroll
    for (int n = 0; n < 4; n++) wmma::fill_fragment(acc[n], 0.f);

    // Convert W2 (64x64) -> Bs
#pragma unroll
    for (int j = 0; j < 4; j++) {
        int id = t + 256 * j;            // 0..1023
        int kk = id >> 4, q = id & 15;
        float4 v = *(const float4*)(W + (size_t)kk * HID + q * 4);
        *(__half2*)&Bs[kk][q * 4]     = __floats2half2_rn(v.x, v.y);
        *(__half2*)&Bs[kk][q * 4 + 2] = __floats2half2_rn(v.z, v.w);
    }

    // Convert A = relu(dinv*agg1 + b1) -> fp16
#pragma unroll
    for (int j = 0; j < 8; j++) {
        int id = t + 256 * j;
        int r = id >> 4, q = id & 15;
        int grow = row0 + r;
        float4 h = make_float4(0.f, 0.f, 0.f, 0.f);
        if (grow < N) {
            float4 v = *(const float4*)(g_agg1 + (size_t)grow * HID + q * 4);
            float dv = g_dinv[grow];
            h.x = fmaxf(fmaf(v.x, dv, __ldg(b1 + q * 4 + 0)), 0.f);
            h.y = fmaxf(fmaf(v.y, dv, __ldg(b1 + q * 4 + 1)), 0.f);
            h.z = fmaxf(fmaf(v.z, dv, __ldg(b1 + q * 4 + 2)), 0.f);
            h.w = fmaxf(fmaf(v.w, dv, __ldg(b1 + q * 4 + 3)), 0.f);
        }
        *(__half2*)&As[r][q * 4]     = __floats2half2_rn(h.x, h.y);
        *(__half2*)&As[r][q * 4 + 2] = __floats2half2_rn(h.z, h.w);
    }
    __syncthreads();

#pragma unroll
    for (int ks = 0; ks < 4; ks++) {
        wmma::fragment<wmma::matrix_a, 16, 16, 16, __half, wmma::row_major> a;
        wmma::load_matrix_sync(a, &As[wid * 16][ks * 16], 72);
#pragma unroll
        for (int n = 0; n < 4; n++) {
            wmma::fragment<wmma::matrix_b, 16, 16, 16, __half, wmma::row_major> b;
            wmma::load_matrix_sync(b, &Bs[ks * 16][n * 16], 72);
            wmma::mma_sync(acc[n], a, b, acc[n]);
        }
    }

    // Epilogue: scale by dinv[row], convert to fp16.
    int r = lane >> 1, c8 = (lane & 1) * 8;
    int grow = row0 + wid * 16 + r;
    float dv = (grow < N) ? g_dinv[grow] : 0.f;
#pragma unroll
    for (int n = 0; n < 4; n++) {
        wmma::store_matrix_sync(&Ps[wid][0][0], acc[n], 20, wmma::mem_row_major);
        __syncwarp();
        if (grow < N) {
            float4 f0 = *(float4*)&Ps[wid][r][c8];
            float4 f1 = *(float4*)&Ps[wid][r][c8 + 4];
            __half2 h0 = __floats2half2_rn(f0.x * dv, f0.y * dv);
            __half2 h1 = __floats2half2_rn(f0.z * dv, f0.w * dv);
            __half2 h2 = __floats2half2_rn(f1.x * dv, f1.y * dv);
            __half2 h3 = __floats2half2_rn(f1.z * dv, f1.w * dv);
            uint4 pk = make_uint4(*(unsigned*)&h0, *(unsigned*)&h1,
                                  *(unsigned*)&h2, *(unsigned*)&h3);
            *(uint4*)(g_feat2h + (size_t)grow * HID + n * 16 + c8) = pk;
        }
        __syncwarp();
    }
}

// Layer-2 aggregate FUSED with classifier (fp16 gather, fp32 accumulate).
__global__ __launch_bounds__(256) void k_agg_out(const float* __restrict__ b2,
                                                 const float* __restrict__ Wc,
                                                 const float* __restrict__ bc,
                                                 float* __restrict__ out, int N) {
    int gtid = blockIdx.x * blockDim.x + threadIdx.x;
    int v = gtid >> 5;
    if (v >= N) return;
    int lane = threadIdx.x & 31;
    int beg = g_rowptr[v];
    int end = g_rowptr[v + 1];

    float2 acc = __half22float2(*((const __half2*)(g_feat2h + (size_t)v * HID) + lane));

    for (int b = beg; b < end; b += 32) {
        int n = end - b;
        if (n > 32) n = 32;
        int s = (lane < n) ? g_csrc[b + lane] : 0;
#pragma unroll 4
        for (int j = 0; j < n; j++) {
            int sj = __shfl_sync(0xffffffffu, s, j);
            float2 w = __half22float2(*((const __half2*)(g_feat2h + (size_t)sj * HID) + lane));
            acc.x += w.x;
            acc.y += w.y;
        }
    }
    float dv = g_dinv[v];
    float h0 = fmaxf(fmaf(acc.x, dv, __ldg(b2 + lane * 2 + 0)), 0.f);
    float h1 = fmaxf(fmaf(acc.y, dv, __ldg(b2 + lane * 2 + 1)), 0.f);
    float p = h0 * __ldg(Wc + lane * 2) + h1 * __ldg(Wc + lane * 2 + 1);
#pragma unroll
    for (int o = 16; o > 0; o >>= 1) p += __shfl_down_sync(0xffffffffu, p, o);
    if (lane == 0) out[v] = p + __ldg(bc);
}

extern "C" void kernel_launch(void* const* d_in, const int* in_sizes, int n_in,
                              void* d_out, int out_size) {
    const float* x  = (const float*)d_in[0];
    const int*   ei = (const int*)d_in[1];
    const float* W1 = (const float*)d_in[2];
    const float* b1 = (const float*)d_in[3];
    const float* W2 = (const float*)d_in[4];
    const float* b2 = (const float*)d_in[5];
    const float* Wc = (const float*)d_in[6];
    const float* bc = (const float*)d_in[7];
    float* out = (float*)d_out;

    int N = in_sizes[0] / INC;
    int E = in_sizes[1] / 2;
    int nb = (N + SCAN_B - 1) / SCAN_B;

    static cudaStream_t s2 = [] {
        cudaStream_t s; cudaStreamCreateWithFlags(&s, cudaStreamNonBlocking); return s;
    }();
    static cudaEvent_t evFork = [] {
        cudaEvent_t e; cudaEventCreateWithFlags(&e, cudaEventDisableTiming); return e;
    }();
    static cudaEvent_t evJoin = [] {
        cudaEvent_t e; cudaEventCreateWithFlags(&e, cudaEventDisableTiming); return e;
    }();

    void* degp = 0;
    cudaGetSymbolAddress(&degp, g_deg);

    // Fork: CSR build on s2, concurrent with gemm1 on the main stream.
    cudaEventRecord(evFork, 0);
    cudaStreamWaitEvent(s2, evFork, 0);
    cudaMemsetAsync(degp, 0, (size_t)N * sizeof(int), s2);
    k_deg<<<(E + 255) / 256, 256, 0, s2>>>(ei, E);
    k_scan1<<<nb, SCAN_B, 0, s2>>>(N);
    k_finalize<<<nb, 256, 0, s2>>>(N);
    k_fill<<<(E + 255) / 256, 256, 0, s2>>>(ei, E);
    cudaEventRecord(evJoin, s2);

    // Main stream: layer-1 GEMM (no dinv dependency).
    k_gemm1<<<(N + 127) / 128, 256>>>(x, W1, N);

    // Join, then the serial tail.
    cudaStreamWaitEvent(0, evJoin, 0);
    k_aggregate1<<<(N * 32 + 255) / 256, 256>>>(N);
    k_gemm2<<<(N + 127) / 128, 256>>>(W2, b1, N);
    k_agg_out<<<(N * 32 + 255) / 256, 256>>>(b2, Wc, bc, out, N);
}

// round 14
// speedup vs baseline: 1.6372x; 1.0650x over previous
#include <cuda_runtime.h>
#include <cuda_fp16.h>
#include <mma.h>
#include <math.h>

using namespace nvcuda;

#define INC 128
#define HID 64
#define MAXN 100000
#define MAXE 1600000
#define SCAN_B 256

__device__ int    g_deg [MAXN];
__device__ int    g_incl[MAXN];
__device__ int    g_bsum[512];
__device__ int    g_rowptr[MAXN + 1];
__device__ int    g_rank[MAXE];
__device__ int    g_csrc[MAXE];
__device__ float  g_dinv[MAXN];
__device__ __half g_feat1h[(size_t)MAXN * HID];   // dinv ⊙ (x@W1) (fp16)
__device__ __half g_h1h  [(size_t)MAXN * HID];    // relu(dinv*agg1 + b1) (fp16)
__device__ __half g_feat2h[(size_t)MAXN * HID];   // dinv ⊙ (h1@W2) (fp16)

// Degree count; atomic return value = edge's rank within its dst bucket.
__global__ void k_deg(const int* __restrict__ ei, int E) {
    int e = blockIdx.x * blockDim.x + threadIdx.x;
    if (e < E) g_rank[e] = atomicAdd(&g_deg[ei[(size_t)E + e]], 1);
}

// Pass 1: per-block inclusive scan of deg (+ dinv)
__global__ void k_scan1(int n) {
    __shared__ int s[SCAN_B];
    int i = blockIdx.x * SCAN_B + threadIdx.x;
    int v = (i < n) ? g_deg[i] : 0;
    if (i < n) g_dinv[i] = rsqrtf((float)(v + 1));   // +1 self-loop
    s[threadIdx.x] = v;
    __syncthreads();
#pragma unroll
    for (int o = 1; o < SCAN_B; o <<= 1) {
        int t = 0;
        if (threadIdx.x >= o) t = s[threadIdx.x - o];
        __syncthreads();
        s[threadIdx.x] += t;
        __syncthreads();
    }
    if (i < n) g_incl[i] = s[threadIdx.x];
    if (threadIdx.x == SCAN_B - 1) g_bsum[blockIdx.x] = s[SCAN_B - 1];
}

// Pass 2 (fused): each block reduces bsum[0..bid) itself, then writes rowptr.
__global__ void k_finalize(int n) {
    __shared__ int red[256];
    int bid = blockIdx.x;
    int t = threadIdx.x;
    int p = 0;
    if (t < bid) p = g_bsum[t];
    if (t + 256 < bid) p += g_bsum[t + 256];
    red[t] = p;
    __syncthreads();
#pragma unroll
    for (int o = 128; o > 0; o >>= 1) {
        if (t < o) red[t] += red[t + o];
        __syncthreads();
    }
    int boff = red[0];
    int i = bid * 256 + t;
    if (i < n) {
        g_rowptr[i + 1] = g_incl[i] + boff;
        if (i == 0) g_rowptr[0] = 0;
    }
}

// Atomic-free fill: pos = rowptr[dst] + rank
__global__ void k_fill(const int* __restrict__ ei, int E) {
    int e = blockIdx.x * blockDim.x + threadIdx.x;
    if (e >= E) return;
    int d = ei[(size_t)E + e];
    g_csrc[g_rowptr[d] + g_rank[e]] = ei[e];
}

// GEMM1 (WMMA fp16): g_feat1h = fp16(dinv ⊙ (x @ W1)).
// CTA = 128 rows x 64 cols, 8 warps, K=128 in two 64-chunks.
__global__ __launch_bounds__(256) void k_gemm1(const float* __restrict__ x,
                                               const float* __restrict__ W,
                                               int N) {
    __shared__ __half As[128][72];
    __shared__ __half Bs[128][72];
    __shared__ float  Ps[8][16][20];
    int t = threadIdx.x;
    int wid = t >> 5, lane = t & 31;
    int row0 = blockIdx.x * 128;

    wmma::fragment<wmma::accumulator, 16, 16, 16, float> acc[4];
#pragma unroll
    for (int n = 0; n < 4; n++) wmma::fill_fragment(acc[n], 0.f);

    // Convert W1 (128x64 fp32) -> Bs fp16, once.
#pragma unroll
    for (int j = 0; j < 8; j++) {
        int id = t + 256 * j;
        int kk = id >> 4, q = id & 15;
        float4 v = *(const float4*)(W + (size_t)kk * HID + q * 4);
        *(__half2*)&Bs[kk][q * 4]     = __floats2half2_rn(v.x, v.y);
        *(__half2*)&Bs[kk][q * 4 + 2] = __floats2half2_rn(v.z, v.w);
    }

#pragma unroll
    for (int kc = 0; kc < 2; kc++) {
#pragma unroll
        for (int j = 0; j < 8; j++) {
            int id = t + 256 * j;
            int r = id >> 4, q = id & 15;
            int grow = row0 + r;
            float4 v = make_float4(0.f, 0.f, 0.f, 0.f);
            if (grow < N)
                v = *(const float4*)(x + (size_t)grow * INC + kc * 64 + q * 4);
            *(__half2*)&As[r][q * 4]     = __floats2half2_rn(v.x, v.y);
            *(__half2*)&As[r][q * 4 + 2] = __floats2half2_rn(v.z, v.w);
        }
        __syncthreads();

#pragma unroll
        for (int ks = 0; ks < 4; ks++) {
            wmma::fragment<wmma::matrix_a, 16, 16, 16, __half, wmma::row_major> a;
            wmma::load_matrix_sync(a, &As[wid * 16][ks * 16], 72);
#pragma unroll
            for (int n = 0; n < 4; n++) {
                wmma::fragment<wmma::matrix_b, 16, 16, 16, __half, wmma::row_major> b;
                wmma::load_matrix_sync(b, &Bs[kc * 64 + ks * 16][n * 16], 72);
                wmma::mma_sync(acc[n], a, b, acc[n]);
            }
        }
        __syncthreads();
    }

    // Epilogue: scale by dinv[row], fp16 store.
    int r = lane >> 1, c8 = (lane & 1) * 8;
    int grow = row0 + wid * 16 + r;
    float dv = (grow < N) ? g_dinv[grow] : 0.f;
#pragma unroll
    for (int n = 0; n < 4; n++) {
        wmma::store_matrix_sync(&Ps[wid][0][0], acc[n], 20, wmma::mem_row_major);
        __syncwarp();
        if (grow < N) {
            float4 f0 = *(float4*)&Ps[wid][r][c8];
            float4 f1 = *(float4*)&Ps[wid][r][c8 + 4];
            __half2 h0 = __floats2half2_rn(f0.x * dv, f0.y * dv);
            __half2 h1 = __floats2half2_rn(f0.z * dv, f0.w * dv);
            __half2 h2 = __floats2half2_rn(f1.x * dv, f1.y * dv);
            __half2 h3 = __floats2half2_rn(f1.z * dv, f1.w * dv);
            uint4 pk = make_uint4(*(unsigned*)&h0, *(unsigned*)&h1,
                                  *(unsigned*)&h2, *(unsigned*)&h3);
            *(uint4*)(g_feat1h + (size_t)grow * HID + n * 16 + c8) = pk;
        }
        __syncwarp();
    }
}

// Layer-1 aggregate + layer-1 epilogue: g_h1h[v] = fp16(relu(dinv[v]*acc + b1)),
// acc = feat1h[v] + sum_{src} feat1h[src]   (messages pre-scaled by dinv[src]).
__global__ __launch_bounds__(256) void k_aggregate1(const float* __restrict__ b1, int N) {
    int gtid = blockIdx.x * blockDim.x + threadIdx.x;
    int v = gtid >> 5;
    if (v >= N) return;
    int lane = threadIdx.x & 31;
    int beg = g_rowptr[v];
    int end = g_rowptr[v + 1];

    float2 acc = __half22float2(*((const __half2*)(g_feat1h + (size_t)v * HID) + lane));

    for (int b = beg; b < end; b += 32) {
        int n = end - b;
        if (n > 32) n = 32;
        int s = (lane < n) ? g_csrc[b + lane] : 0;
#pragma unroll 8
        for (int j = 0; j < n; j++) {
            int sj = __shfl_sync(0xffffffffu, s, j);
            float2 w = __half22float2(*((const __half2*)(g_feat1h + (size_t)sj * HID) + lane));
            acc.x += w.x;
            acc.y += w.y;
        }
    }
    float dv = g_dinv[v];
    float h0 = fmaxf(fmaf(acc.x, dv, __ldg(b1 + lane * 2 + 0)), 0.f);
    float h1 = fmaxf(fmaf(acc.y, dv, __ldg(b1 + lane * 2 + 1)), 0.f);
    __half2 hp = __floats2half2_rn(h0, h1);
    *((__half2*)(g_h1h + (size_t)v * HID) + lane) = hp;
}

// GEMM2 (WMMA fp16): g_feat2h = fp16(dinv ⊙ (h1 @ W2)); A = g_h1h (fp16, direct copy).
__global__ __launch_bounds__(256) void k_gemm2(const float* __restrict__ W,
                                               int N) {
    __shared__ __half As[128][72];
    __shared__ __half Bs[64][72];
    __shared__ float  Ps[8][16][20];
    int t = threadIdx.x;
    int wid = t >> 5, lane = t & 31;
    int row0 = blockIdx.x * 128;

    wmma::fragment<wmma::accumulator, 16, 16, 16, float> acc[4];
#pragma unroll
    for (int n = 0; n < 4; n++) wmma::fill_fragment(acc[n], 0.f);

    // Convert W2 (64x64 fp32) -> Bs
#pragma unroll
    for (int j = 0; j < 4; j++) {
        int id = t + 256 * j;
        int kk = id >> 4, q = id & 15;
        float4 v = *(const float4*)(W + (size_t)kk * HID + q * 4);
        *(__half2*)&Bs[kk][q * 4]     = __floats2half2_rn(v.x, v.y);
        *(__half2*)&Bs[kk][q * 4 + 2] = __floats2half2_rn(v.z, v.w);
    }

    // Copy A = g_h1h (already fp16): 128 rows x 64 halves = 1024 uint4.
#pragma unroll
    for (int j = 0; j < 4; j++) {
        int id = t + 256 * j;
        int r = id >> 3, q = id & 7;
        int grow = row0 + r;
        uint4 v = make_uint4(0, 0, 0, 0);
        if (grow < N) v = *(const uint4*)(g_h1h + (size_t)grow * HID + q * 8);
        *(uint4*)&As[r][q * 8] = v;
    }
    __syncthreads();

#pragma unroll
    for (int ks = 0; ks < 4; ks++) {
        wmma::fragment<wmma::matrix_a, 16, 16, 16, __half, wmma::row_major> a;
        wmma::load_matrix_sync(a, &As[wid * 16][ks * 16], 72);
#pragma unroll
        for (int n = 0; n < 4; n++) {
            wmma::fragment<wmma::matrix_b, 16, 16, 16, __half, wmma::row_major> b;
            wmma::load_matrix_sync(b, &Bs[ks * 16][n * 16], 72);
            wmma::mma_sync(acc[n], a, b, acc[n]);
        }
    }

    // Epilogue: scale by dinv[row], fp16 store.
    int r = lane >> 1, c8 = (lane & 1) * 8;
    int grow = row0 + wid * 16 + r;
    float dv = (grow < N) ? g_dinv[grow] : 0.f;
#pragma unroll
    for (int n = 0; n < 4; n++) {
        wmma::store_matrix_sync(&Ps[wid][0][0], acc[n], 20, wmma::mem_row_major);
        __syncwarp();
        if (grow < N) {
            float4 f0 = *(float4*)&Ps[wid][r][c8];
            float4 f1 = *(float4*)&Ps[wid][r][c8 + 4];
            __half2 h0 = __floats2half2_rn(f0.x * dv, f0.y * dv);
            __half2 h1 = __floats2half2_rn(f0.z * dv, f0.w * dv);
            __half2 h2 = __floats2half2_rn(f1.x * dv, f1.y * dv);
            __half2 h3 = __floats2half2_rn(f1.z * dv, f1.w * dv);
            uint4 pk = make_uint4(*(unsigned*)&h0, *(unsigned*)&h1,
                                  *(unsigned*)&h2, *(unsigned*)&h3);
            *(uint4*)(g_feat2h + (size_t)grow * HID + n * 16 + c8) = pk;
        }
        __syncwarp();
    }
}

// Layer-2 aggregate FUSED with classifier (fp16 gather, fp32 accumulate).
__global__ __launch_bounds__(256) void k_agg_out(const float* __restrict__ b2,
                                                 const float* __restrict__ Wc,
                                                 const float* __restrict__ bc,
                                                 float* __restrict__ out, int N) {
    int gtid = blockIdx.x * blockDim.x + threadIdx.x;
    int v = gtid >> 5;
    if (v >= N) return;
    int lane = threadIdx.x & 31;
    int beg = g_rowptr[v];
    int end = g_rowptr[v + 1];

    float2 acc = __half22float2(*((const __half2*)(g_feat2h + (size_t)v * HID) + lane));

    for (int b = beg; b < end; b += 32) {
        int n = end - b;
        if (n > 32) n = 32;
        int s = (lane < n) ? g_csrc[b + lane] : 0;
#pragma unroll 8
        for (int j = 0; j < n; j++) {
            int sj = __shfl_sync(0xffffffffu, s, j);
            float2 w = __half22float2(*((const __half2*)(g_feat2h + (size_t)sj * HID) + lane));
            acc.x += w.x;
            acc.y += w.y;
        }
    }
    float dv = g_dinv[v];
    float h0 = fmaxf(fmaf(acc.x, dv, __ldg(b2 + lane * 2 + 0)), 0.f);
    float h1 = fmaxf(fmaf(acc.y, dv, __ldg(b2 + lane * 2 + 1)), 0.f);
    float p = h0 * __ldg(Wc + lane * 2) + h1 * __ldg(Wc + lane * 2 + 1);
#pragma unroll
    for (int o = 16; o > 0; o >>= 1) p += __shfl_down_sync(0xffffffffu, p, o);
    if (lane == 0) out[v] = p + __ldg(bc);
}

extern "C" void kernel_launch(void* const* d_in, const int* in_sizes, int n_in,
                              void* d_out, int out_size) {
    const float* x  = (const float*)d_in[0];
    const int*   ei = (const int*)d_in[1];
    const float* W1 = (const float*)d_in[2];
    const float* b1 = (const float*)d_in[3];
    const float* W2 = (const float*)d_in[4];
    const float* b2 = (const float*)d_in[5];
    const float* Wc = (const float*)d_in[6];
    const float* bc = (const float*)d_in[7];
    float* out = (float*)d_out;

    int N = in_sizes[0] / INC;
    int E = in_sizes[1] / 2;
    int nb = (N + SCAN_B - 1) / SCAN_B;

    static cudaStream_t s2 = [] {
        cudaStream_t s; cudaStreamCreateWithFlags(&s, cudaStreamNonBlocking); return s;
    }();
    static cudaEvent_t evFork = [] {
        cudaEvent_t e; cudaEventCreateWithFlags(&e, cudaEventDisableTiming); return e;
    }();
    static cudaEvent_t evJoin = [] {
        cudaEvent_t e; cudaEventCreateWithFlags(&e, cudaEventDisableTiming); return e;
    }();

    void* degp = 0;
    cudaGetSymbolAddress(&degp, g_deg);

    // Head (main stream): deg + scan1 produce dinv, needed by gemm1's epilogue.
    cudaMemsetAsync(degp, 0, (size_t)N * sizeof(int));
    k_deg<<<(E + 255) / 256, 256>>>(ei, E);
    k_scan1<<<nb, SCAN_B>>>(N);

    // Fork: finalize+fill (CSR tail) on s2, concurrent with gemm1.
    cudaEventRecord(evFork, 0);
    cudaStreamWaitEvent(s2, evFork, 0);
    k_finalize<<<nb, 256, 0, s2>>>(N);
    k_fill<<<(E + 255) / 256, 256, 0, s2>>>(ei, E);
    cudaEventRecord(evJoin, s2);

    // Main stream: layer-1 GEMM (needs dinv, not CSR).
    k_gemm1<<<(N + 127) / 128, 256>>>(x, W1, N);

    // Join, then the serial tail.
    cudaStreamWaitEvent(0, evJoin, 0);
    k_aggregate1<<<(N * 32 + 255) / 256, 256>>>(b1, N);
    k_gemm2<<<(N + 127) / 128, 256>>>(W2, N);
    k_agg_out<<<(N * 32 + 255) / 256, 256>>>(b2, Wc, bc, out, N);
}